// round 3
// baseline (speedup 1.0000x reference)
#include <cuda_runtime.h>
#include <cstdint>

// ---------------------------------------------------------------------------
// CrossModalAttention: out = softmax(mask((Q Wq+bq)(KV Wk+bk)^T / 32)) (KV Wv+bv) Wo + bo
// B=8, LQ=1024, LKV=2048, QDIM=KDIM=HID=1024
// Round-2: TF32 mma.sync GEMMs + robust mask-dtype canonicalization
// (round-1 failure traced to key_mask device representation: bool is most
//  likely stored as int32; we now detect int32/uint8/float32 from the data).
// ---------------------------------------------------------------------------

#define CB    8
#define CLQ   1024
#define CLKV  2048
#define CHID  1024
#define CQDIM 1024
#define CKDIM 1024

// Scratch (allocation-free rule: __device__ globals)
__device__ float g_Q[(size_t)CB * CLQ * CHID];    // 32 MB
__device__ float g_K[(size_t)CB * CLKV * CHID];   // 64 MB
__device__ float g_V[(size_t)CB * CLKV * CHID];   // 64 MB
__device__ float g_S[(size_t)CB * CLQ * CLKV];    // 64 MB
__device__ float g_C[(size_t)CB * CLQ * CHID];    // 32 MB
__device__ unsigned char g_mask[(size_t)CB * CLKV];

__device__ __forceinline__ uint32_t f2tf(float f) {
    uint32_t u;
    asm("cvt.rna.tf32.f32 %0, %1;" : "=r"(u) : "f"(f));
    return u;
}

__device__ __forceinline__ void mma_tf32(float* c, const uint32_t* a, const uint32_t* b) {
    asm volatile(
        "mma.sync.aligned.m16n8k8.row.col.f32.tf32.tf32.f32 "
        "{%0,%1,%2,%3}, {%4,%5,%6,%7}, {%8,%9}, {%0,%1,%2,%3};\n"
        : "+f"(c[0]), "+f"(c[1]), "+f"(c[2]), "+f"(c[3])
        : "r"(a[0]), "r"(a[1]), "r"(a[2]), "r"(a[3]), "r"(b[0]), "r"(b[1]));
}

// ---------------------------------------------------------------------------
// Mask canonicalization. The harness materializes the bool key_mask as one of
// {int32, uint8, float32}; we detect which from the first 4096 bytes (safe to
// read under all three layouts since B*LKV = 16384 elements >= 4096 bytes):
//   float32: 1.0f = [00 00 80 3F] -> some byte at off%4==3 equals 0x3F
//   int32  : 0/1  = [vv 00 00 00] -> all bytes at off%4 in {1,2,3} are zero
//   uint8  : random 0/1 bytes at every offset (byte at off%4==3 is 0 or 1,
//            never 0x3F)
// Detection is pure function of input data -> deterministic & capturable.
// ---------------------------------------------------------------------------
__global__ __launch_bounds__(256) void mask_canonicalize(const unsigned char* __restrict__ m)
{
    __shared__ int s_nz123, s_f3;
    if (threadIdx.x == 0) { s_nz123 = 0; s_f3 = 0; }
    __syncthreads();

    int nz = 0, f3 = 0;
    const int base = threadIdx.x * 16;
#pragma unroll
    for (int i = 0; i < 16; i++) {
        const int idx = base + i;          // 0..4095 across the block
        const unsigned char v = m[idx];
        const int off = idx & 3;
        if (off != 0 && v != 0) {
            nz = 1;
            if (off == 3 && v == 0x3F) f3 = 1;
        }
    }
    if (nz) atomicOr(&s_nz123, 1);
    if (f3) atomicOr(&s_f3, 1);
    __syncthreads();

    const int mode = s_f3 ? 2 : (s_nz123 ? 1 : 0);  // 2=f32, 1=u8, 0=i32
    const long idx = (long)blockIdx.x * 256 + threadIdx.x;
    unsigned char out;
    if (mode == 0)      out = (((const int*)m)[idx]   != 0);
    else if (mode == 1) out = (m[idx]                 != 0);
    else                out = (((const float*)m)[idx] != 0.0f);
    g_mask[idx] = out;
}

// C[M,N] = alpha * A[M,K] * op(B) + bias
// TRANS_B=false: B is [K,N] row-major (NN)
// TRANS_B=true : B is [N,K] row-major, dot over K (NT)
// All tile dims divide M,N,K exactly for every call in this problem.
template <bool TRANS_B, bool HAS_BIAS>
__global__ __launch_bounds__(256) void gemm_tf32(
    const float* __restrict__ Ag, const float* __restrict__ Bg,
    const float* __restrict__ bias, float* __restrict__ Cg,
    int lda, int ldb, int ldc,
    long sA, long sB, long sC, float alpha)
{
    constexpr int AS_LD = 20;                       // [128][20] -> frag reads conflict-free
    __shared__ uint32_t As[128 * AS_LD];
    __shared__ uint32_t Bs[TRANS_B ? 128 * 20 : 16 * 136];

    const float* Ab = Ag + (long)blockIdx.z * sA;
    const float* Bb = Bg + (long)blockIdx.z * sB;
    float*       Cb = Cg + (long)blockIdx.z * sC;

    const int m_blk = blockIdx.y * 128;
    const int n_blk = blockIdx.x * 128;

    const int tid  = threadIdx.x;
    const int lane = tid & 31;
    const int warp = tid >> 5;
    const int g = lane >> 2;   // groupID
    const int t = lane & 3;    // thread-in-group
    const int wr = (warp >> 2) * 64;  // warp M offset: 0 / 64
    const int wc = (warp & 3) * 32;   // warp N offset: 0..96

    float acc[4][4][4];
#pragma unroll
    for (int i = 0; i < 4; i++)
#pragma unroll
        for (int j = 0; j < 4; j++)
#pragma unroll
            for (int r = 0; r < 4; r++) acc[i][j][r] = 0.f;

    // Global-load assignment (256 threads):
    // A tile 128x16: rows (tid>>2) and +64, float4 at col (tid&3)*4
    const int ar = tid >> 2;
    const int aq = (tid & 3) * 4;
    const float* Aptr0 = Ab + (long)(m_blk + ar) * lda + aq;
    const float* Aptr1 = Aptr0 + (long)64 * lda;

    const float* Bptr0;
    const float* Bptr1;
    const int br = tid >> 5;          // NN: k-row 0..7 (+8)
    const int bc = (tid & 31) * 4;    // NN: n-col float4
    if (TRANS_B) {
        Bptr0 = Bb + (long)(n_blk + ar) * ldb + aq;
        Bptr1 = Bptr0 + (long)64 * ldb;
    } else {
        Bptr0 = Bb + (long)br * ldb + n_blk + bc;
        Bptr1 = Bptr0 + (long)8 * ldb;
    }

    // Prefetch first tile into registers
    float4 ra0 = *(const float4*)Aptr0;
    float4 ra1 = *(const float4*)Aptr1;
    float4 rb0 = *(const float4*)Bptr0;
    float4 rb1 = *(const float4*)Bptr1;

    // K loop bound: lda is the A leading dim == K for all our calls
    const int Kdim = lda;

    for (int k0 = 0; k0 < Kdim; k0 += 16) {
        __syncthreads();  // previous compute done before overwriting smem
        // Stage -> smem (convert to tf32 here)
        {
            uint32_t* d0 = &As[ar * AS_LD + aq];
            d0[0] = f2tf(ra0.x); d0[1] = f2tf(ra0.y); d0[2] = f2tf(ra0.z); d0[3] = f2tf(ra0.w);
            uint32_t* d1 = &As[(ar + 64) * AS_LD + aq];
            d1[0] = f2tf(ra1.x); d1[1] = f2tf(ra1.y); d1[2] = f2tf(ra1.z); d1[3] = f2tf(ra1.w);
            if (TRANS_B) {
                uint32_t* e0 = &Bs[ar * 20 + aq];
                e0[0] = f2tf(rb0.x); e0[1] = f2tf(rb0.y); e0[2] = f2tf(rb0.z); e0[3] = f2tf(rb0.w);
                uint32_t* e1 = &Bs[(ar + 64) * 20 + aq];
                e1[0] = f2tf(rb1.x); e1[1] = f2tf(rb1.y); e1[2] = f2tf(rb1.z); e1[3] = f2tf(rb1.w);
            } else {
                uint32_t* e0 = &Bs[br * 136 + bc];
                e0[0] = f2tf(rb0.x); e0[1] = f2tf(rb0.y); e0[2] = f2tf(rb0.z); e0[3] = f2tf(rb0.w);
                uint32_t* e1 = &Bs[(br + 8) * 136 + bc];
                e1[0] = f2tf(rb1.x); e1[1] = f2tf(rb1.y); e1[2] = f2tf(rb1.z); e1[3] = f2tf(rb1.w);
            }
        }
        __syncthreads();

        // Prefetch next tile (overlaps with compute below)
        if (k0 + 16 < Kdim) {
            Aptr0 += 16; Aptr1 += 16;
            ra0 = *(const float4*)Aptr0;
            ra1 = *(const float4*)Aptr1;
            if (TRANS_B) {
                Bptr0 += 16; Bptr1 += 16;
            } else {
                Bptr0 += (long)16 * ldb; Bptr1 += (long)16 * ldb;
            }
            rb0 = *(const float4*)Bptr0;
            rb1 = *(const float4*)Bptr1;
        }

        // Two k8 MMA steps per stage
#pragma unroll
        for (int ks = 0; ks < 2; ks++) {
            const int kk = ks * 8;
            uint32_t af[4][4];
#pragma unroll
            for (int i = 0; i < 4; i++) {
                const int rb_ = wr + i * 16;
                const uint32_t* p  = &As[(rb_ + g) * AS_LD + kk + t];
                const uint32_t* p2 = p + 8 * AS_LD;
                af[i][0] = p[0];   // (g,   t)
                af[i][1] = p2[0];  // (g+8, t)
                af[i][2] = p[4];   // (g,   t+4)
                af[i][3] = p2[4];  // (g+8, t+4)
            }
            uint32_t bf[4][2];
#pragma unroll
            for (int j = 0; j < 4; j++) {
                const int nb = wc + j * 8;
                if (TRANS_B) {
                    const uint32_t* p = &Bs[(nb + g) * 20 + kk + t];
                    bf[j][0] = p[0];  // (k=t,   n=g)
                    bf[j][1] = p[4];  // (k=t+4, n=g)
                } else {
                    bf[j][0] = Bs[(kk + t) * 136 + nb + g];
                    bf[j][1] = Bs[(kk + t + 4) * 136 + nb + g];
                }
            }
#pragma unroll
            for (int i = 0; i < 4; i++)
#pragma unroll
                for (int j = 0; j < 4; j++) mma_tf32(acc[i][j], af[i], bf[j]);
        }
    }

    // Epilogue: alpha * acc + bias
#pragma unroll
    for (int i = 0; i < 4; i++) {
        const int r0 = m_blk + wr + i * 16 + g;
#pragma unroll
        for (int j = 0; j < 4; j++) {
            const int cn = n_blk + wc + j * 8 + 2 * t;
            float b0v = 0.f, b1v = 0.f;
            if (HAS_BIAS) { b0v = bias[cn]; b1v = bias[cn + 1]; }
            float2 v0 = make_float2(alpha * acc[i][j][0] + b0v, alpha * acc[i][j][1] + b1v);
            float2 v1 = make_float2(alpha * acc[i][j][2] + b0v, alpha * acc[i][j][3] + b1v);
            *(float2*)&Cb[(long)r0 * ldc + cn]       = v0;
            *(float2*)&Cb[(long)(r0 + 8) * ldc + cn] = v1;
        }
    }
}

// Masked softmax over rows of S[B*LQ, LKV]; scale already applied in scores GEMM.
__global__ __launch_bounds__(256) void softmax_rows(float* __restrict__ S)
{
    const int row = blockIdx.x;            // 0 .. B*LQ-1
    const int b   = row / CLQ;
    float* s = S + (long)row * CLKV;
    const unsigned char* mrow = g_mask + (long)b * CLKV;

    const int tid = threadIdx.x;
    const int w = tid >> 5, l = tid & 31;

    float v[8];
    float mx = -3.0e38f;
#pragma unroll
    for (int i = 0; i < 8; i++) {
        const int k = tid + i * 256;
        const float x = mrow[k] ? s[k] : -1e9f;   // identical to reference where()
        v[i] = x;
        mx = fmaxf(mx, x);
    }

    __shared__ float red[8];
    // block max
#pragma unroll
    for (int o = 16; o > 0; o >>= 1) mx = fmaxf(mx, __shfl_xor_sync(0xffffffffu, mx, o));
    if (l == 0) red[w] = mx;
    __syncthreads();
    if (w == 0) {
        float m8 = (l < 8) ? red[l] : -3.0e38f;
#pragma unroll
        for (int o = 4; o > 0; o >>= 1) m8 = fmaxf(m8, __shfl_xor_sync(0xffffffffu, m8, o));
        if (l == 0) red[0] = m8;
    }
    __syncthreads();
    mx = red[0];
    __syncthreads();  // red reused below

    float sum = 0.f;
#pragma unroll
    for (int i = 0; i < 8; i++) { v[i] = __expf(v[i] - mx); sum += v[i]; }
#pragma unroll
    for (int o = 16; o > 0; o >>= 1) sum += __shfl_xor_sync(0xffffffffu, sum, o);
    if (l == 0) red[w] = sum;
    __syncthreads();
    if (w == 0) {
        float s8 = (l < 8) ? red[l] : 0.f;
#pragma unroll
        for (int o = 4; o > 0; o >>= 1) s8 += __shfl_xor_sync(0xffffffffu, s8, o);
        if (l == 0) red[0] = s8;
    }
    __syncthreads();
    const float inv = 1.0f / red[0];
#pragma unroll
    for (int i = 0; i < 8; i++) s[tid + i * 256] = v[i] * inv;
}

extern "C" void kernel_launch(void* const* d_in, const int* in_sizes, int n_in,
                              void* d_out, int out_size)
{
    (void)in_sizes; (void)n_in; (void)out_size;
    const float* query = (const float*)d_in[0];
    const float* keyv  = (const float*)d_in[1];
    const unsigned char* mask = (const unsigned char*)d_in[2];
    const float* Wq = (const float*)d_in[3];
    const float* bq = (const float*)d_in[4];
    const float* Wk = (const float*)d_in[5];
    const float* bk = (const float*)d_in[6];
    const float* Wv = (const float*)d_in[7];
    const float* bv = (const float*)d_in[8];
    const float* Wo = (const float*)d_in[9];
    const float* bo = (const float*)d_in[10];
    float* out = (float*)d_out;

    float *Qb, *Kb, *Vb, *Sb, *Cb;
    cudaGetSymbolAddress((void**)&Qb, g_Q);
    cudaGetSymbolAddress((void**)&Kb, g_K);
    cudaGetSymbolAddress((void**)&Vb, g_V);
    cudaGetSymbolAddress((void**)&Sb, g_S);
    cudaGetSymbolAddress((void**)&Cb, g_C);

    const dim3 blk(256, 1, 1);

    // Canonicalize mask (dtype auto-detect) into g_mask
    mask_canonicalize<<<(CB * CLKV) / 256, 256>>>(mask);

    // Q = query @ Wq + bq        [8192,1024] x [1024,1024]
    gemm_tf32<false, true><<<dim3(CHID / 128, (CB * CLQ) / 128, 1), blk>>>(
        query, Wq, bq, Qb, CQDIM, CHID, CHID, 0, 0, 0, 1.f);
    // K = keyv @ Wk + bk         [16384,1024] x [1024,1024]
    gemm_tf32<false, true><<<dim3(CHID / 128, (CB * CLKV) / 128, 1), blk>>>(
        keyv, Wk, bk, Kb, CKDIM, CHID, CHID, 0, 0, 0, 1.f);
    // V = keyv @ Wv + bv
    gemm_tf32<false, true><<<dim3(CHID / 128, (CB * CLKV) / 128, 1), blk>>>(
        keyv, Wv, bv, Vb, CKDIM, CHID, CHID, 0, 0, 0, 1.f);
    // S = (Q K^T) / 32           batched NT: per-b [1024,1024] x [2048,1024]^T
    gemm_tf32<true, false><<<dim3(CLKV / 128, CLQ / 128, CB), blk>>>(
        Qb, Kb, nullptr, Sb, CHID, CHID, CLKV,
        (long)CLQ * CHID, (long)CLKV * CHID, (long)CLQ * CLKV, 0.03125f);
    // P = softmax(mask(S))
    softmax_rows<<<CB * CLQ, 256>>>(Sb);
    // Ctx = P @ V                batched NN: [1024,2048] x [2048,1024]
    gemm_tf32<false, false><<<dim3(CHID / 128, CLQ / 128, CB), blk>>>(
        Sb, Vb, nullptr, Cb, CLKV, CHID, CHID,
        (long)CLQ * CLKV, (long)CLKV * CHID, (long)CLQ * CHID, 1.f);
    // out = Ctx @ Wo + bo        [8192,1024] x [1024,1024]
    gemm_tf32<false, true><<<dim3(CQDIM / 128, (CB * CLQ) / 128, 1), blk>>>(
        Cb, Wo, bo, out, CHID, CQDIM, CQDIM, 0, 0, 0, 1.f);
}

// round 9
// speedup vs baseline: 1.9696x; 1.9696x over previous
#include <cuda_runtime.h>
#include <cuda_fp16.h>
#include <cstdint>

// ---------------------------------------------------------------------------
// CrossModalAttention on plain sm_100 (tcgen05 unavailable in this build).
// Legacy mma.sync FP16 GEMMs (m16n8k16, f32 accum): 2x tf32 MAC rate, half
// the operand bytes. fp16 keeps tf32's 11-bit significand; all tensors here
// are range-safe. All GEMMs NT (A [M,K] fp16, B [N,K] fp16).
// Round-9 bisect: STATIC 40KB shared memory + NO cudaFuncSetAttribute.
// (Every executed round used static smem; every container death carried
//  cudaFuncSetAttribute + dynamic smem -- likely illegal under the
//  harness's global-mode graph capture.)
// ---------------------------------------------------------------------------

#define CB    8
#define CLQ   1024
#define CLKV  2048
#define CHID  1024

// -------------------- scratch (allocation-free: device globals) -------------
__device__ __align__(16) __half g_qh [(size_t)CB * CLQ  * CHID];  // query fp16
__device__ __align__(16) __half g_kvh[(size_t)CB * CLKV * CHID];  // key_value fp16
__device__ __align__(16) __half g_Qh [(size_t)CB * CLQ  * CHID];
__device__ __align__(16) __half g_Kh [(size_t)CB * CLKV * CHID];
__device__ __align__(16) __half g_Vth[(size_t)CB * CHID * CLKV];  // V transposed [b][h][lkv]
__device__ __align__(16) __half g_Ph [(size_t)CB * CLQ  * CLKV];  // softmax probs
__device__ __align__(16) __half g_Ch [(size_t)CB * CLQ  * CHID];  // context
__device__ __align__(16) float  g_S  [(size_t)CB * CLQ  * CLKV];  // raw scores f32
__device__ __align__(16) __half g_Wh [4][(size_t)CHID * CHID];    // Wq^T..Wo^T fp16
__device__ unsigned char g_mask[(size_t)CB * CLKV];

// -------------------- helpers ----------------------------------------------
__device__ __forceinline__ uint32_t smem_u32(const void* p) {
    uint32_t a;
    asm("{ .reg .u64 t; cvta.to.shared.u64 t, %1; cvt.u32.u64 %0, t; }" : "=r"(a) : "l"(p));
    return a;
}
__device__ __forceinline__ void cpa16(uint32_t s, const void* g) {
    asm volatile("cp.async.cg.shared.global [%0], [%1], 16;" :: "r"(s), "l"(g));
}
#define CP_COMMIT() asm volatile("cp.async.commit_group;" ::: "memory")
#define CP_WAIT1()  asm volatile("cp.async.wait_group 1;" ::: "memory")

__device__ __forceinline__ void mma_f16(float* c, const uint32_t* a, const uint32_t* b) {
    asm volatile(
        "mma.sync.aligned.m16n8k16.row.col.f32.f16.f16.f32 "
        "{%0,%1,%2,%3}, {%4,%5,%6,%7}, {%8,%9}, {%0,%1,%2,%3};\n"
        : "+f"(c[0]), "+f"(c[1]), "+f"(c[2]), "+f"(c[3])
        : "r"(a[0]), "r"(a[1]), "r"(a[2]), "r"(a[3]), "r"(b[0]), "r"(b[1]));
}

// -------------------- universal fp16 NT GEMM --------------------------------
// OMODE: 0 = f32 out, 1 = fp16 out, 2 = fp16 transposed out (V projection)
// C = alpha * A[M,K] @ B[N,K]^T (+ bias).  Tiles 128x128, k-chunk 32.
// smem row stride 80B (64B data + 16B pad): fragment LDS bank = (20g+t)%32,
// all 32 distinct -> conflict-free.  Double-buffered (2 stages, 40KB static).
static constexpr int A_BYTES     = 128 * 80;          // 10240
static constexpr int STAGE_BYTES = 2 * A_BYTES;       // 20480

template <int OMODE, bool BIAS>
__global__ __launch_bounds__(256, 2) void gemm_f16(
    const __half* __restrict__ Ag, const __half* __restrict__ Bg,
    const float* __restrict__ bias, void* __restrict__ Cg,
    int Kdim, int ldc, long sA, long sB, long sC, float alpha)
{
    __shared__ __align__(128) char smem[2 * STAGE_BYTES];   // 40KB static
    const uint32_t sb = smem_u32(smem);
    const int tid = threadIdx.x;

    const int m_blk = blockIdx.y * 128;
    const int n_blk = blockIdx.x * 128;
    const __half* Abase = Ag + (size_t)blockIdx.z * sA + (size_t)m_blk * Kdim;
    const __half* Bbase = Bg + (size_t)blockIdx.z * sB + (size_t)n_blk * Kdim;

    const int NC = Kdim / 32;

    // cp.async staging: 512 16B-chunks per tile, 2 per thread per tile.
    const int r0c = tid >> 2,         c0c = tid & 3;
    const int r1c = (tid + 256) >> 2, c1c = (tid + 256) & 3;

    auto load = [&](int kc, int st) {
        const uint32_t s0 = sb + st * STAGE_BYTES;
        cpa16(s0 + r0c * 80 + c0c * 16,           Abase + (size_t)r0c * Kdim + kc * 32 + c0c * 8);
        cpa16(s0 + r1c * 80 + c1c * 16,           Abase + (size_t)r1c * Kdim + kc * 32 + c1c * 8);
        cpa16(s0 + A_BYTES + r0c * 80 + c0c * 16, Bbase + (size_t)r0c * Kdim + kc * 32 + c0c * 8);
        cpa16(s0 + A_BYTES + r1c * 80 + c1c * 16, Bbase + (size_t)r1c * Kdim + kc * 32 + c1c * 8);
    };

    float acc[4][4][4];
#pragma unroll
    for (int i = 0; i < 4; i++)
#pragma unroll
        for (int j = 0; j < 4; j++)
#pragma unroll
            for (int r = 0; r < 4; r++) acc[i][j][r] = 0.f;

    const int w = tid >> 5, l = tid & 31;
    const int g = l >> 2, t = l & 3;
    const int wr = (w >> 2) * 64;   // warp M offset 0/64
    const int wc = (w & 3) * 32;    // warp N offset 0..96

    // prologue: chunk 0 into stage 0
    load(0, 0); CP_COMMIT();

    for (int c = 0; c < NC; c++) {
        if (c + 1 < NC) load(c + 1, (c + 1) & 1);
        CP_COMMIT();                              // (possibly empty group in tail)
        CP_WAIT1();                               // chunk c resident
        __syncthreads();

        const char* stA = smem + (c & 1) * STAGE_BYTES;
        const char* stB = stA + A_BYTES;
#pragma unroll
        for (int ks = 0; ks < 2; ks++) {
            const int kb = ks * 32 + t * 4;       // byte offset within 64B row
            uint32_t af[4][4];
#pragma unroll
            for (int i = 0; i < 4; i++) {
                const char* p = stA + (wr + i * 16 + g) * 80 + kb;
                af[i][0] = *(const uint32_t*)(p);
                af[i][1] = *(const uint32_t*)(p + 8 * 80);
                af[i][2] = *(const uint32_t*)(p + 16);
                af[i][3] = *(const uint32_t*)(p + 8 * 80 + 16);
            }
            uint32_t bf[4][2];
#pragma unroll
            for (int j = 0; j < 4; j++) {
                const char* p = stB + (wc + j * 8 + g) * 80 + kb;
                bf[j][0] = *(const uint32_t*)(p);
                bf[j][1] = *(const uint32_t*)(p + 16);
            }
#pragma unroll
            for (int i = 0; i < 4; i++)
#pragma unroll
                for (int j = 0; j < 4; j++) mma_f16(acc[i][j], af[i], bf[j]);
        }
        __syncthreads();                          // reads done before stage reuse
    }

    // epilogue
#pragma unroll
    for (int i = 0; i < 4; i++) {
        const int row0 = m_blk + wr + i * 16 + g;
        const int row1 = row0 + 8;
#pragma unroll
        for (int j = 0; j < 4; j++) {
            const int col = n_blk + wc + j * 8 + 2 * t;
            float c0 = alpha * acc[i][j][0], c1 = alpha * acc[i][j][1];
            float c2 = alpha * acc[i][j][2], c3 = alpha * acc[i][j][3];
            float b0 = 0.f, b1 = 0.f;
            if (BIAS) { b0 = bias[col]; b1 = bias[col + 1]; }
            if (OMODE == 0) {
                float* C = (float*)Cg + (size_t)blockIdx.z * sC;
                *(float2*)&C[(size_t)row0 * ldc + col] = make_float2(c0 + b0, c1 + b1);
                *(float2*)&C[(size_t)row1 * ldc + col] = make_float2(c2 + b0, c3 + b1);
            } else if (OMODE == 1) {
                __half* C = (__half*)Cg + (size_t)blockIdx.z * sC;
                *(__half2*)&C[(size_t)row0 * ldc + col] = __floats2half2_rn(c0 + b0, c1 + b1);
                *(__half2*)&C[(size_t)row1 * ldc + col] = __floats2half2_rn(c2 + b0, c3 + b1);
            } else {
                // V transposed: Vt[b][h=col][lkv=row]
                const int b = row0 >> 11, lkv0 = row0 & 2047, lkv1 = row1 & 2047;
                __half* vt = (__half*)Cg + (size_t)b * CHID * CLKV;
                vt[(size_t)(col)     * CLKV + lkv0] = __float2half(c0 + b0);
                vt[(size_t)(col + 1) * CLKV + lkv0] = __float2half(c1 + b1);
                vt[(size_t)(col)     * CLKV + lkv1] = __float2half(c2 + b0);
                vt[(size_t)(col + 1) * CLKV + lkv1] = __float2half(c3 + b1);
            }
        }
    }
}

// -------------------- mask canonicalization (validated round 3) -------------
__global__ __launch_bounds__(256) void mask_canonicalize(const unsigned char* __restrict__ m)
{
    __shared__ int s_nz123, s_f3;
    if (threadIdx.x == 0) { s_nz123 = 0; s_f3 = 0; }
    __syncthreads();
    int nz = 0, f3 = 0;
    const int base = threadIdx.x * 16;
#pragma unroll
    for (int i = 0; i < 16; i++) {
        const int idx = base + i;
        const unsigned char v = m[idx];
        const int offb = idx & 3;
        if (offb != 0 && v != 0) { nz = 1; if (offb == 3 && v == 0x3F) f3 = 1; }
    }
    if (nz) atomicOr(&s_nz123, 1);
    if (f3) atomicOr(&s_f3, 1);
    __syncthreads();
    const int mode = s_f3 ? 2 : (s_nz123 ? 1 : 0);
    const long idx = (long)blockIdx.x * 256 + threadIdx.x;
    unsigned char out;
    if (mode == 0)      out = (((const int*)m)[idx]   != 0);
    else if (mode == 1) out = (m[idx]                 != 0);
    else                out = (((const float*)m)[idx] != 0.0f);
    g_mask[idx] = out;
}

// -------------------- masked softmax: f32 scores -> fp16 probs --------------
__global__ __launch_bounds__(256) void softmax_rows(const float* __restrict__ S,
                                                    __half* __restrict__ P)
{
    const int row = blockIdx.x;
    const int b   = row / CLQ;
    const float* s = S + (long)row * CLKV;
    __half* p = P + (long)row * CLKV;
    const unsigned char* mrow = g_mask + (long)b * CLKV;

    const int tid = threadIdx.x;
    const int w = tid >> 5, l = tid & 31;
    float v[8];
    float mx = -3.0e38f;
#pragma unroll
    for (int i = 0; i < 8; i++) {
        const int k = tid + i * 256;
        const float x = mrow[k] ? s[k] : -1e9f;
        v[i] = x; mx = fmaxf(mx, x);
    }
    __shared__ float red[8];
#pragma unroll
    for (int o = 16; o > 0; o >>= 1) mx = fmaxf(mx, __shfl_xor_sync(0xffffffffu, mx, o));
    if (l == 0) red[w] = mx;
    __syncthreads();
    if (w == 0) {
        float m8 = (l < 8) ? red[l] : -3.0e38f;
#pragma unroll
        for (int o = 4; o > 0; o >>= 1) m8 = fmaxf(m8, __shfl_xor_sync(0xffffffffu, m8, o));
        if (l == 0) red[0] = m8;
    }
    __syncthreads();
    mx = red[0];
    __syncthreads();
    float sum = 0.f;
#pragma unroll
    for (int i = 0; i < 8; i++) { v[i] = __expf(v[i] - mx); sum += v[i]; }
#pragma unroll
    for (int o = 16; o > 0; o >>= 1) sum += __shfl_xor_sync(0xffffffffu, sum, o);
    if (l == 0) red[w] = sum;
    __syncthreads();
    if (w == 0) {
        float s8 = (l < 8) ? red[l] : 0.f;
#pragma unroll
        for (int o = 4; o > 0; o >>= 1) s8 += __shfl_xor_sync(0xffffffffu, s8, o);
        if (l == 0) red[0] = s8;
    }
    __syncthreads();
    const float inv = 1.0f / red[0];
#pragma unroll
    for (int i = 0; i < 8; i++) p[tid + i * 256] = __float2half(v[i] * inv);
}

// -------------------- operand preparation -----------------------------------
__global__ __launch_bounds__(256) void h_convert(const float4* __restrict__ in,
                                                 __half2* __restrict__ out, int n4)
{
    const int i = blockIdx.x * 256 + threadIdx.x;
    if (i < n4) {
        float4 v = in[i];
        out[2 * i]     = __floats2half2_rn(v.x, v.y);
        out[2 * i + 1] = __floats2half2_rn(v.z, v.w);
    }
}

// Wt[n][k] = fp16(W[k][n]), 1024x1024
__global__ __launch_bounds__(256) void transpose_h(const float* __restrict__ W,
                                                   __half* __restrict__ Wt)
{
    __shared__ float tbuf[32][33];
    const int bx = blockIdx.x * 32, by = blockIdx.y * 32;
    const int x = threadIdx.x & 31, y8 = threadIdx.x >> 5;
#pragma unroll
    for (int i = 0; i < 32; i += 8)
        tbuf[y8 + i][x] = W[(size_t)(by + y8 + i) * CHID + bx + x];
    __syncthreads();
#pragma unroll
    for (int i = 0; i < 32; i += 8)
        Wt[(size_t)(bx + y8 + i) * CHID + by + x] = __float2half(tbuf[x][y8 + i]);
}

// -------------------- launch -------------------------------------------------
extern "C" void kernel_launch(void* const* d_in, const int* in_sizes, int n_in,
                              void* d_out, int out_size)
{
    (void)in_sizes; (void)n_in; (void)out_size;
    const float* query = (const float*)d_in[0];
    const float* keyv  = (const float*)d_in[1];
    const unsigned char* mask = (const unsigned char*)d_in[2];
    const float* Wq = (const float*)d_in[3];
    const float* bq = (const float*)d_in[4];
    const float* Wk = (const float*)d_in[5];
    const float* bk = (const float*)d_in[6];
    const float* Wv = (const float*)d_in[7];
    const float* bv = (const float*)d_in[8];
    const float* Wo = (const float*)d_in[9];
    const float* bo = (const float*)d_in[10];
    float* out = (float*)d_out;

    __half *qh, *kvh, *Qh, *Kh, *Vth, *Ph, *Ch, *Wh;
    float* Sf;
    cudaGetSymbolAddress((void**)&qh,  g_qh);
    cudaGetSymbolAddress((void**)&kvh, g_kvh);
    cudaGetSymbolAddress((void**)&Qh,  g_Qh);
    cudaGetSymbolAddress((void**)&Kh,  g_Kh);
    cudaGetSymbolAddress((void**)&Vth, g_Vth);
    cudaGetSymbolAddress((void**)&Ph,  g_Ph);
    cudaGetSymbolAddress((void**)&Ch,  g_Ch);
    cudaGetSymbolAddress((void**)&Sf,  g_S);
    cudaGetSymbolAddress((void**)&Wh,  g_Wh);

    // prep
    mask_canonicalize<<<(CB * CLKV) / 256, 256>>>(mask);
    h_convert<<<(CB * CLQ  * CHID / 4) / 256, 256>>>((const float4*)query, (__half2*)qh,
                                                     CB * CLQ * CHID / 4);
    h_convert<<<(CB * CLKV * CHID / 4) / 256, 256>>>((const float4*)keyv, (__half2*)kvh,
                                                     CB * CLKV * CHID / 4);
    transpose_h<<<dim3(32, 32), 256>>>(Wq, Wh + 0L * CHID * CHID);
    transpose_h<<<dim3(32, 32), 256>>>(Wk, Wh + 1L * CHID * CHID);
    transpose_h<<<dim3(32, 32), 256>>>(Wv, Wh + 2L * CHID * CHID);
    transpose_h<<<dim3(32, 32), 256>>>(Wo, Wh + 3L * CHID * CHID);

    const dim3 blk(256, 1, 1);
    // Q = qh @ WqT + bq -> fp16
    gemm_f16<1, true><<<dim3(8, 64, 1), blk>>>(
        qh, Wh + 0L * CHID * CHID, bq, Qh, CHID, CHID, 0, 0, 0, 1.f);
    // K = kvh @ WkT + bk -> fp16
    gemm_f16<1, true><<<dim3(8, 128, 1), blk>>>(
        kvh, Wh + 1L * CHID * CHID, bk, Kh, CHID, CHID, 0, 0, 0, 1.f);
    // Vt = (kvh @ WvT + bv)^T -> fp16 [b][h][lkv]
    gemm_f16<2, true><<<dim3(8, 128, 1), blk>>>(
        kvh, Wh + 2L * CHID * CHID, bv, Vth, CHID, 0, 0, 0, 0, 1.f);
    // S = (Q K^T)/32 -> f32 (batched)
    gemm_f16<0, false><<<dim3(16, 8, CB), blk>>>(
        Qh, Kh, nullptr, Sf, CHID, CLKV,
        (long)CLQ * CHID, (long)CLKV * CHID, (long)CLQ * CLKV, 0.03125f);
    // P = softmax(mask(S)) -> fp16
    softmax_rows<<<CB * CLQ, 256>>>(Sf, Ph);
    // Ctx = P @ Vt^T -> fp16 (batched, K = LKV)
    gemm_f16<1, false><<<dim3(8, 8, CB), blk>>>(
        Ph, Vth, nullptr, Ch, CLKV, CHID,
        (long)CLQ * CLKV, (long)CHID * CLKV, (long)CLQ * CHID, 1.f);
    // out = Ctx @ WoT + bo -> f32
    gemm_f16<0, true><<<dim3(8, 64, 1), blk>>>(
        Ch, Wh + 3L * CHID * CHID, bo, out, CHID, CHID, 0, 0, 0, 1.f);
}

// round 10
// speedup vs baseline: 1.9841x; 1.0074x over previous
#include <cuda_runtime.h>
#include <cuda_fp16.h>
#include <cstdint>

// ---------------------------------------------------------------------------
// CrossModalAttention, plain sm_100, legacy mma.sync FP16 (m16n8k16, f32 acc).
// R9 passed at 773.6us (~97% of legacy-HMMA ceiling in-kernel). R10: attack
// wave-quantization tails: Q/K/V projections merged into ONE launch
// (2560 CTAs = 8.65 waves vs 3 launches totaling ~16% tail loss), prep fused
// into 2 launches (also puts the ctx GEMM at ncu's -s 5 capture slot).
// Static smem only; NO cudaFuncSetAttribute (proven container-killer).
// ---------------------------------------------------------------------------

#define CB    8
#define CLQ   1024
#define CLKV  2048
#define CHID  1024

// -------------------- scratch (allocation-free: device globals) -------------
__device__ __align__(16) __half g_qh [(size_t)CB * CLQ  * CHID];  // query fp16
__device__ __align__(16) __half g_kvh[(size_t)CB * CLKV * CHID];  // key_value fp16
__device__ __align__(16) __half g_Qh [(size_t)CB * CLQ  * CHID];
__device__ __align__(16) __half g_Kh [(size_t)CB * CLKV * CHID];
__device__ __align__(16) __half g_Vth[(size_t)CB * CHID * CLKV];  // V transposed [b][h][lkv]
__device__ __align__(16) __half g_Ph [(size_t)CB * CLQ  * CLKV];  // softmax probs
__device__ __align__(16) __half g_Ch [(size_t)CB * CLQ  * CHID];  // context
__device__ __align__(16) float  g_S  [(size_t)CB * CLQ  * CLKV];  // raw scores f32
__device__ __align__(16) __half g_Wh [4][(size_t)CHID * CHID];    // Wq^T..Wo^T fp16
__device__ unsigned char g_mask[(size_t)CB * CLKV];

// -------------------- helpers ----------------------------------------------
__device__ __forceinline__ uint32_t smem_u32(const void* p) {
    uint32_t a;
    asm("{ .reg .u64 t; cvta.to.shared.u64 t, %1; cvt.u32.u64 %0, t; }" : "=r"(a) : "l"(p));
    return a;
}
__device__ __forceinline__ void cpa16(uint32_t s, const void* g) {
    asm volatile("cp.async.cg.shared.global [%0], [%1], 16;" :: "r"(s), "l"(g));
}
#define CP_COMMIT() asm volatile("cp.async.commit_group;" ::: "memory")
#define CP_WAIT1()  asm volatile("cp.async.wait_group 1;" ::: "memory")

__device__ __forceinline__ void mma_f16(float* c, const uint32_t* a, const uint32_t* b) {
    asm volatile(
        "mma.sync.aligned.m16n8k16.row.col.f32.f16.f16.f32 "
        "{%0,%1,%2,%3}, {%4,%5,%6,%7}, {%8,%9}, {%0,%1,%2,%3};\n"
        : "+f"(c[0]), "+f"(c[1]), "+f"(c[2]), "+f"(c[3])
        : "r"(a[0]), "r"(a[1]), "r"(a[2]), "r"(a[3]), "r"(b[0]), "r"(b[1]));
}

// -------------------- shared GEMM machinery ---------------------------------
// Tiles 128x128, k-chunk 32, double-buffered static smem (40KB), 256 threads.
// smem row stride 80B (64B data + 16B pad): fragment LDS bank = (20g+t)%32,
// all distinct -> conflict-free.
static constexpr int A_BYTES     = 128 * 80;          // 10240
static constexpr int STAGE_BYTES = 2 * A_BYTES;       // 20480

// Mainloop: accumulates C_tile(128x128) = A[M,K] @ B[N,K]^T for one CTA tile.
// acc is [i][j][r] as in the epilogues below. Validated in R9.
__device__ __forceinline__ void gemm_mainloop(
    char* smem, uint32_t sb,
    const __half* __restrict__ Abase, const __half* __restrict__ Bbase,
    int Kdim, float acc[4][4][4])
{
    const int tid = threadIdx.x;
    const int r0c = tid >> 2,         c0c = tid & 3;
    const int r1c = (tid + 256) >> 2, c1c = (tid + 256) & 3;
    const int NC = Kdim / 32;

    auto load = [&](int kc, int st) {
        const uint32_t s0 = sb + st * STAGE_BYTES;
        cpa16(s0 + r0c * 80 + c0c * 16,           Abase + (size_t)r0c * Kdim + kc * 32 + c0c * 8);
        cpa16(s0 + r1c * 80 + c1c * 16,           Abase + (size_t)r1c * Kdim + kc * 32 + c1c * 8);
        cpa16(s0 + A_BYTES + r0c * 80 + c0c * 16, Bbase + (size_t)r0c * Kdim + kc * 32 + c0c * 8);
        cpa16(s0 + A_BYTES + r1c * 80 + c1c * 16, Bbase + (size_t)r1c * Kdim + kc * 32 + c1c * 8);
    };

    const int w = tid >> 5, l = tid & 31;
    const int g = l >> 2, t = l & 3;
    const int wr = (w >> 2) * 64;
    const int wc = (w & 3) * 32;

    load(0, 0); CP_COMMIT();

    for (int c = 0; c < NC; c++) {
        if (c + 1 < NC) load(c + 1, (c + 1) & 1);
        CP_COMMIT();
        CP_WAIT1();
        __syncthreads();

        const char* stA = smem + (c & 1) * STAGE_BYTES;
        const char* stB = stA + A_BYTES;
#pragma unroll
        for (int ks = 0; ks < 2; ks++) {
            const int kb = ks * 32 + t * 4;
            uint32_t af[4][4];
#pragma unroll
            for (int i = 0; i < 4; i++) {
                const char* p = stA + (wr + i * 16 + g) * 80 + kb;
                af[i][0] = *(const uint32_t*)(p);
                af[i][1] = *(const uint32_t*)(p + 8 * 80);
                af[i][2] = *(const uint32_t*)(p + 16);
                af[i][3] = *(const uint32_t*)(p + 8 * 80 + 16);
            }
            uint32_t bf[4][2];
#pragma unroll
            for (int j = 0; j < 4; j++) {
                const char* p = stB + (wc + j * 8 + g) * 80 + kb;
                bf[j][0] = *(const uint32_t*)(p);
                bf[j][1] = *(const uint32_t*)(p + 16);
            }
#pragma unroll
            for (int i = 0; i < 4; i++)
#pragma unroll
                for (int j = 0; j < 4; j++) mma_f16(acc[i][j], af[i], bf[j]);
        }
        __syncthreads();
    }
}

// -------------------- merged Q/K/V projection (one launch, 2560 CTAs) -------
// grid (8, 320): by<64 -> Q proj; by<192 -> K proj; else V proj (transposed).
__global__ __launch_bounds__(256, 2) void proj_all(
    const __half* __restrict__ qh, const __half* __restrict__ kvh,
    const __half* __restrict__ Wh,
    const float* __restrict__ bq, const float* __restrict__ bk,
    const float* __restrict__ bv,
    __half* __restrict__ Qh, __half* __restrict__ Kh, __half* __restrict__ Vth)
{
    __shared__ __align__(128) char smem[2 * STAGE_BYTES];
    const uint32_t sb = smem_u32(smem);
    const int by = blockIdx.y;

    const __half* Abase;
    const __half* Bbase;
    const float* bias;
    __half* Cout;
    int m_blk;
    int omode;                       // 1 = normal fp16 out, 2 = transposed (V)
    if (by < 64) {
        m_blk = by * 128;
        Abase = qh + (size_t)m_blk * CHID;
        Bbase = Wh + 0L * CHID * CHID;
        bias = bq; Cout = Qh; omode = 1;
    } else if (by < 192) {
        m_blk = (by - 64) * 128;
        Abase = kvh + (size_t)m_blk * CHID;
        Bbase = Wh + 1L * CHID * CHID;
        bias = bk; Cout = Kh; omode = 1;
    } else {
        m_blk = (by - 192) * 128;
        Abase = kvh + (size_t)m_blk * CHID;
        Bbase = Wh + 2L * CHID * CHID;
        bias = bv; Cout = Vth; omode = 2;
    }
    const int n_blk = blockIdx.x * 128;
    Bbase += (size_t)n_blk * CHID;

    float acc[4][4][4];
#pragma unroll
    for (int i = 0; i < 4; i++)
#pragma unroll
        for (int j = 0; j < 4; j++)
#pragma unroll
            for (int r = 0; r < 4; r++) acc[i][j][r] = 0.f;

    gemm_mainloop(smem, sb, Abase, Bbase, CHID, acc);

    const int tid = threadIdx.x;
    const int w = tid >> 5, l = tid & 31;
    const int g = l >> 2, t = l & 3;
    const int wr = (w >> 2) * 64, wc = (w & 3) * 32;

#pragma unroll
    for (int i = 0; i < 4; i++) {
        const int row0 = m_blk + wr + i * 16 + g;
        const int row1 = row0 + 8;
#pragma unroll
        for (int j = 0; j < 4; j++) {
            const int col = n_blk + wc + j * 8 + 2 * t;
            const float b0 = bias[col], b1 = bias[col + 1];
            const float c0 = acc[i][j][0] + b0, c1 = acc[i][j][1] + b1;
            const float c2 = acc[i][j][2] + b0, c3 = acc[i][j][3] + b1;
            if (omode == 1) {
                *(__half2*)&Cout[(size_t)row0 * CHID + col] = __floats2half2_rn(c0, c1);
                *(__half2*)&Cout[(size_t)row1 * CHID + col] = __floats2half2_rn(c2, c3);
            } else {
                const int b = row0 >> 11, lkv0 = row0 & 2047, lkv1 = row1 & 2047;
                __half* vt = Vth + (size_t)b * CHID * CLKV;
                vt[(size_t)(col)     * CLKV + lkv0] = __float2half(c0);
                vt[(size_t)(col + 1) * CLKV + lkv0] = __float2half(c1);
                vt[(size_t)(col)     * CLKV + lkv1] = __float2half(c2);
                vt[(size_t)(col + 1) * CLKV + lkv1] = __float2half(c3);
            }
        }
    }
}

// -------------------- generic GEMM (scores / ctx / out) ----------------------
// OMODE: 0 = f32 out, 1 = fp16 out
template <int OMODE, bool BIAS>
__global__ __launch_bounds__(256, 2) void gemm_f16(
    const __half* __restrict__ Ag, const __half* __restrict__ Bg,
    const float* __restrict__ bias, void* __restrict__ Cg,
    int Kdim, int ldc, long sA, long sB, long sC, float alpha)
{
    __shared__ __align__(128) char smem[2 * STAGE_BYTES];
    const uint32_t sb = smem_u32(smem);

    const int m_blk = blockIdx.y * 128;
    const int n_blk = blockIdx.x * 128;
    const __half* Abase = Ag + (size_t)blockIdx.z * sA + (size_t)m_blk * Kdim;
    const __half* Bbase = Bg + (size_t)blockIdx.z * sB + (size_t)n_blk * Kdim;

    float acc[4][4][4];
#pragma unroll
    for (int i = 0; i < 4; i++)
#pragma unroll
        for (int j = 0; j < 4; j++)
#pragma unroll
            for (int r = 0; r < 4; r++) acc[i][j][r] = 0.f;

    gemm_mainloop(smem, sb, Abase, Bbase, Kdim, acc);

    const int tid = threadIdx.x;
    const int w = tid >> 5, l = tid & 31;
    const int g = l >> 2, t = l & 3;
    const int wr = (w >> 2) * 64, wc = (w & 3) * 32;

#pragma unroll
    for (int i = 0; i < 4; i++) {
        const int row0 = m_blk + wr + i * 16 + g;
        const int row1 = row0 + 8;
#pragma unroll
        for (int j = 0; j < 4; j++) {
            const int col = n_blk + wc + j * 8 + 2 * t;
            float c0 = alpha * acc[i][j][0], c1 = alpha * acc[i][j][1];
            float c2 = alpha * acc[i][j][2], c3 = alpha * acc[i][j][3];
            if (BIAS) {
                const float b0 = bias[col], b1 = bias[col + 1];
                c0 += b0; c1 += b1; c2 += b0; c3 += b1;
            }
            if (OMODE == 0) {
                float* C = (float*)Cg + (size_t)blockIdx.z * sC;
                *(float2*)&C[(size_t)row0 * ldc + col] = make_float2(c0, c1);
                *(float2*)&C[(size_t)row1 * ldc + col] = make_float2(c2, c3);
            } else {
                __half* C = (__half*)Cg + (size_t)blockIdx.z * sC;
                *(__half2*)&C[(size_t)row0 * ldc + col] = __floats2half2_rn(c0, c1);
                *(__half2*)&C[(size_t)row1 * ldc + col] = __floats2half2_rn(c2, c3);
            }
        }
    }
}

// -------------------- fused prep 1: mask canonicalize + fp16 converts --------
// grid: [0,64) mask | [64, 64+8192) query convert | [64+8192, 64+8192+16384) kv
__global__ __launch_bounds__(256) void prep_fused(
    const unsigned char* __restrict__ m,
    const float4* __restrict__ q, const float4* __restrict__ kv)
{
    const int bx = blockIdx.x;
    const int tid = threadIdx.x;
    if (bx < 64) {
        // mask canonicalize (validated R3): detect int32/uint8/float32
        __shared__ int s_nz123, s_f3;
        if (tid == 0) { s_nz123 = 0; s_f3 = 0; }
        __syncthreads();
        int nz = 0, f3 = 0;
        const int base = tid * 16;
#pragma unroll
        for (int i = 0; i < 16; i++) {
            const int idx = base + i;
            const unsigned char v = m[idx];
            const int offb = idx & 3;
            if (offb != 0 && v != 0) { nz = 1; if (offb == 3 && v == 0x3F) f3 = 1; }
        }
        if (nz) atomicOr(&s_nz123, 1);
        if (f3) atomicOr(&s_f3, 1);
        __syncthreads();
        const int mode = s_f3 ? 2 : (s_nz123 ? 1 : 0);
        const long idx = (long)bx * 256 + tid;
        unsigned char out;
        if (mode == 0)      out = (((const int*)m)[idx]   != 0);
        else if (mode == 1) out = (m[idx]                 != 0);
        else                out = (((const float*)m)[idx] != 0.0f);
        g_mask[idx] = out;
    } else if (bx < 64 + 8192) {
        const long i = (long)(bx - 64) * 256 + tid;
        float4 v = q[i];
        __half2* out = (__half2*)g_qh;
        out[2 * i]     = __floats2half2_rn(v.x, v.y);
        out[2 * i + 1] = __floats2half2_rn(v.z, v.w);
    } else {
        const long i = (long)(bx - 64 - 8192) * 256 + tid;
        float4 v = kv[i];
        __half2* out = (__half2*)g_kvh;
        out[2 * i]     = __floats2half2_rn(v.x, v.y);
        out[2 * i + 1] = __floats2half2_rn(v.z, v.w);
    }
}

// -------------------- fused prep 2: 4 weight transposes (grid.z selects) -----
__global__ __launch_bounds__(256) void transpose4_h(
    const float* __restrict__ W0, const float* __restrict__ W1,
    const float* __restrict__ W2, const float* __restrict__ W3)
{
    const int z = blockIdx.z;
    const float* W = (z == 0) ? W0 : (z == 1) ? W1 : (z == 2) ? W2 : W3;
    __half* Wt = (__half*)g_Wh + (size_t)z * CHID * CHID;

    __shared__ float tbuf[32][33];
    const int bx = blockIdx.x * 32, by = blockIdx.y * 32;
    const int x = threadIdx.x & 31, y8 = threadIdx.x >> 5;
#pragma unroll
    for (int i = 0; i < 32; i += 8)
        tbuf[y8 + i][x] = W[(size_t)(by + y8 + i) * CHID + bx + x];
    __syncthreads();
#pragma unroll
    for (int i = 0; i < 32; i += 8)
        Wt[(size_t)(bx + y8 + i) * CHID + by + x] = __float2half(tbuf[x][y8 + i]);
}

// -------------------- masked softmax: f32 scores -> fp16 probs --------------
__global__ __launch_bounds__(256) void softmax_rows(const float* __restrict__ S,
                                                    __half* __restrict__ P)
{
    const int row = blockIdx.x;
    const int b   = row / CLQ;
    const float* s = S + (long)row * CLKV;
    __half* p = P + (long)row * CLKV;
    const unsigned char* mrow = g_mask + (long)b * CLKV;

    const int tid = threadIdx.x;
    const int w = tid >> 5, l = tid & 31;
    float v[8];
    float mx = -3.0e38f;
#pragma unroll
    for (int i = 0; i < 8; i++) {
        const int k = tid + i * 256;
        const float x = mrow[k] ? s[k] : -1e9f;
        v[i] = x; mx = fmaxf(mx, x);
    }
    __shared__ float red[8];
#pragma unroll
    for (int o = 16; o > 0; o >>= 1) mx = fmaxf(mx, __shfl_xor_sync(0xffffffffu, mx, o));
    if (l == 0) red[w] = mx;
    __syncthreads();
    if (w == 0) {
        float m8 = (l < 8) ? red[l] : -3.0e38f;
#pragma unroll
        for (int o = 4; o > 0; o >>= 1) m8 = fmaxf(m8, __shfl_xor_sync(0xffffffffu, m8, o));
        if (l == 0) red[0] = m8;
    }
    __syncthreads();
    mx = red[0];
    __syncthreads();
    float sum = 0.f;
#pragma unroll
    for (int i = 0; i < 8; i++) { v[i] = __expf(v[i] - mx); sum += v[i]; }
#pragma unroll
    for (int o = 16; o > 0; o >>= 1) sum += __shfl_xor_sync(0xffffffffu, sum, o);
    if (l == 0) red[w] = sum;
    __syncthreads();
    if (w == 0) {
        float s8 = (l < 8) ? red[l] : 0.f;
#pragma unroll
        for (int o = 4; o > 0; o >>= 1) s8 += __shfl_xor_sync(0xffffffffu, s8, o);
        if (l == 0) red[0] = s8;
    }
    __syncthreads();
    const float inv = 1.0f / red[0];
#pragma unroll
    for (int i = 0; i < 8; i++) p[tid + i * 256] = __float2half(v[i] * inv);
}

// -------------------- launch -------------------------------------------------
extern "C" void kernel_launch(void* const* d_in, const int* in_sizes, int n_in,
                              void* d_out, int out_size)
{
    (void)in_sizes; (void)n_in; (void)out_size;
    const float* query = (const float*)d_in[0];
    const float* keyv  = (const float*)d_in[1];
    const unsigned char* mask = (const unsigned char*)d_in[2];
    const float* Wq = (const float*)d_in[3];
    const float* bq = (const float*)d_in[4];
    const float* Wk = (const float*)d_in[5];
    const float* bk = (const float*)d_in[6];
    const float* Wv = (const float*)d_in[7];
    const float* bv = (const float*)d_in[8];
    const float* Wo = (const float*)d_in[9];
    const float* bo = (const float*)d_in[10];
    float* out = (float*)d_out;

    __half *qh, *kvh, *Qh, *Kh, *Vth, *Ph, *Ch, *Wh;
    float* Sf;
    cudaGetSymbolAddress((void**)&qh,  g_qh);
    cudaGetSymbolAddress((void**)&kvh, g_kvh);
    cudaGetSymbolAddress((void**)&Qh,  g_Qh);
    cudaGetSymbolAddress((void**)&Kh,  g_Kh);
    cudaGetSymbolAddress((void**)&Vth, g_Vth);
    cudaGetSymbolAddress((void**)&Ph,  g_Ph);
    cudaGetSymbolAddress((void**)&Ch,  g_Ch);
    cudaGetSymbolAddress((void**)&Sf,  g_S);
    cudaGetSymbolAddress((void**)&Wh,  g_Wh);

    // launch 0: mask + fp16 converts (fused)
    prep_fused<<<64 + 8192 + 16384, 256>>>(mask, (const float4*)query, (const float4*)keyv);
    // launch 1: all 4 weight transposes (fused)
    transpose4_h<<<dim3(32, 32, 4), 256>>>(Wq, Wk, Wv, Wo);
    // launch 2: merged Q/K/V projections (2560 CTAs -> 8.65 waves)
    proj_all<<<dim3(8, 320, 1), 256>>>(qh, kvh, Wh, bq, bk, bv, Qh, Kh, Vth);
    // launch 3: S = (Q K^T)/32 -> f32 (batched)
    gemm_f16<0, false><<<dim3(16, 8, CB), 256>>>(
        Qh, Kh, nullptr, Sf, CHID, CLKV,
        (long)CLQ * CHID, (long)CLKV * CHID, (long)CLQ * CLKV, 0.03125f);
    // launch 4: P = softmax(mask(S)) -> fp16
    softmax_rows<<<CB * CLQ, 256>>>(Sf, Ph);
    // launch 5 (ncu -s 5 capture slot): Ctx = P @ Vt^T -> fp16 (batched)
    gemm_f16<1, false><<<dim3(8, 8, CB), 256>>>(
        Ph, Vth, nullptr, Ch, CLKV, CHID,
        (long)CLQ * CLKV, (long)CHID * CLKV, (long)CLQ * CHID, 1.f);
    // launch 6: out = Ctx @ WoT + bo -> f32
    gemm_f16<0, true><<<dim3(8, 64, 1), 256>>>(
        Ch, Wh + 3L * CHID * CHID, bo, out, CHID, CHID, 0, 0, 0, 1.f);
}

// round 12
// speedup vs baseline: 2.1818x; 1.0997x over previous
#include <cuda_runtime.h>
#include <cuda_fp16.h>
#include <cstdint>

// ---------------------------------------------------------------------------
// CrossModalAttention, plain sm_100, legacy mma.sync FP16 (m16n8k16, f32 acc).
// R10: 768us, scores GEMM tensor=44.8% -> HMMA starved by 48 scalar LDS per
// k-chunk. R11/R12: ldmatrix.m8n8.x4 fragment loads (12 LDSM/chunk; 2x fewer
// crossbar phases; shorter dep chains). R11 died to a container flake with
// host code byte-identical to the twice-proven R10; resubmitting per
// discipline (smem +16B pad, offsets hoisted -- semantically null tweaks).
// Static smem only; NO cudaFuncSetAttribute (proven container-killer).
// ---------------------------------------------------------------------------

#define CB    8
#define CLQ   1024
#define CLKV  2048
#define CHID  1024

// -------------------- scratch (allocation-free: device globals) -------------
__device__ __align__(16) __half g_qh [(size_t)CB * CLQ  * CHID];  // query fp16
__device__ __align__(16) __half g_kvh[(size_t)CB * CLKV * CHID];  // key_value fp16
__device__ __align__(16) __half g_Qh [(size_t)CB * CLQ  * CHID];
__device__ __align__(16) __half g_Kh [(size_t)CB * CLKV * CHID];
__device__ __align__(16) __half g_Vth[(size_t)CB * CHID * CLKV];  // V transposed [b][h][lkv]
__device__ __align__(16) __half g_Ph [(size_t)CB * CLQ  * CLKV];  // softmax probs
__device__ __align__(16) __half g_Ch [(size_t)CB * CLQ  * CHID];  // context
__device__ __align__(16) float  g_S  [(size_t)CB * CLQ  * CLKV];  // raw scores f32
__device__ __align__(16) __half g_Wh [4][(size_t)CHID * CHID];    // Wq^T..Wo^T fp16
__device__ unsigned char g_mask[(size_t)CB * CLKV];

// -------------------- helpers ----------------------------------------------
__device__ __forceinline__ uint32_t smem_u32(const void* p) {
    uint32_t a;
    asm("{ .reg .u64 t; cvta.to.shared.u64 t, %1; cvt.u32.u64 %0, t; }" : "=r"(a) : "l"(p));
    return a;
}
__device__ __forceinline__ void cpa16(uint32_t s, const void* g) {
    asm volatile("cp.async.cg.shared.global [%0], [%1], 16;" :: "r"(s), "l"(g));
}
#define CP_COMMIT() asm volatile("cp.async.commit_group;" ::: "memory")
#define CP_WAIT1()  asm volatile("cp.async.wait_group 1;" ::: "memory")

__device__ __forceinline__ void mma_f16(float* c, const uint32_t* a, const uint32_t* b) {
    asm volatile(
        "mma.sync.aligned.m16n8k16.row.col.f32.f16.f16.f32 "
        "{%0,%1,%2,%3}, {%4,%5,%6,%7}, {%8,%9}, {%0,%1,%2,%3};\n"
        : "+f"(c[0]), "+f"(c[1]), "+f"(c[2]), "+f"(c[3])
        : "r"(a[0]), "r"(a[1]), "r"(a[2]), "r"(a[3]), "r"(b[0]), "r"(b[1]));
}
__device__ __forceinline__ void ldsm4(uint32_t* r, uint32_t a) {
    asm volatile("ldmatrix.sync.aligned.m8n8.x4.shared.b16 {%0,%1,%2,%3}, [%4];"
        : "=r"(r[0]), "=r"(r[1]), "=r"(r[2]), "=r"(r[3]) : "r"(a));
}

// -------------------- shared GEMM machinery ---------------------------------
// Tiles 128x128, k-chunk 32, double-buffered static smem (40KB+pad), 256 thr.
// smem row stride 80B (64B data + 16B pad). ldmatrix phase check: banks of
// row r are r*20+{0..3} mod 32 -> 8 rows tile all 32 banks, conflict-free.
static constexpr int A_BYTES     = 128 * 80;          // 10240
static constexpr int STAGE_BYTES = 2 * A_BYTES;       // 20480

// Mainloop: C_tile(128x128) = A[M,K] @ B[N,K]^T, ldmatrix fragment loads.
__device__ __forceinline__ void gemm_mainloop(
    uint32_t sb,
    const __half* __restrict__ Abase, const __half* __restrict__ Bbase,
    int Kdim, float acc[4][4][4])
{
    const int tid = threadIdx.x;
    const int r0c = tid >> 2,         c0c = tid & 3;
    const int r1c = (tid + 256) >> 2, c1c = (tid + 256) & 3;
    const int NC = Kdim / 32;

    auto load = [&](int kc, int st) {
        const uint32_t s0 = sb + st * STAGE_BYTES;
        cpa16(s0 + r0c * 80 + c0c * 16,           Abase + (size_t)r0c * Kdim + kc * 32 + c0c * 8);
        cpa16(s0 + r1c * 80 + c1c * 16,           Abase + (size_t)r1c * Kdim + kc * 32 + c1c * 8);
        cpa16(s0 + A_BYTES + r0c * 80 + c0c * 16, Bbase + (size_t)r0c * Kdim + kc * 32 + c0c * 8);
        cpa16(s0 + A_BYTES + r1c * 80 + c1c * 16, Bbase + (size_t)r1c * Kdim + kc * 32 + c1c * 8);
    };

    const int w = tid >> 5, l = tid & 31;
    const int wr = (w >> 2) * 64;
    const int wc = (w & 3) * 32;

    // ldmatrix per-thread address components (x4: matrix idx = l>>3, row = l&7)
    const int lr   = l & 7;
    const int seg  = (l >> 3) & 1;   // idx bit 0
    const int seg2 = (l >> 4) & 1;   // idx bit 1
    // A x4 -> af[i][0..3] = (m+0,k0),(m+8,k0),(m+0,k16B),(m+8,k16B)
    uint32_t aoff0 = (uint32_t)((wr + 0 * 16 + lr + seg * 8) * 80 + seg2 * 16);
    uint32_t aoff1 = (uint32_t)((wr + 1 * 16 + lr + seg * 8) * 80 + seg2 * 16);
    uint32_t aoff2 = (uint32_t)((wr + 2 * 16 + lr + seg * 8) * 80 + seg2 * 16);
    uint32_t aoff3 = (uint32_t)((wr + 3 * 16 + lr + seg * 8) * 80 + seg2 * 16);
    // B x4 (two j's per load) -> (n_j,k0),(n_j,k16B),(n_j+8,k0),(n_j+8,k16B)
    uint32_t boff0 = (uint32_t)(A_BYTES + (wc + 0 * 16 + seg2 * 8 + lr) * 80 + seg * 16);
    uint32_t boff1 = (uint32_t)(A_BYTES + (wc + 1 * 16 + seg2 * 8 + lr) * 80 + seg * 16);

    load(0, 0); CP_COMMIT();

    for (int c = 0; c < NC; c++) {
        if (c + 1 < NC) load(c + 1, (c + 1) & 1);
        CP_COMMIT();
        CP_WAIT1();
        __syncthreads();

        const uint32_t st = sb + (c & 1) * STAGE_BYTES;
#pragma unroll
        for (int ks = 0; ks < 2; ks++) {
            const uint32_t base = st + ks * 32;
            uint32_t af[4][4];
            ldsm4(af[0], base + aoff0);
            ldsm4(af[1], base + aoff1);
            ldsm4(af[2], base + aoff2);
            ldsm4(af[3], base + aoff3);
            uint32_t bq[2][4];
            ldsm4(bq[0], base + boff0);
            ldsm4(bq[1], base + boff1);
#pragma unroll
            for (int i = 0; i < 4; i++)
#pragma unroll
                for (int j = 0; j < 4; j++)
                    mma_f16(acc[i][j], af[i], &bq[j >> 1][(j & 1) * 2]);
        }
        __syncthreads();
    }
}

// -------------------- merged Q/K/V projection (one launch, 2560 CTAs) -------
// grid (8, 320): by<64 -> Q proj; by<192 -> K proj; else V proj (transposed).
__global__ __launch_bounds__(256, 2) void proj_all(
    const __half* __restrict__ qh, const __half* __restrict__ kvh,
    const __half* __restrict__ Wh,
    const float* __restrict__ bq, const float* __restrict__ bk,
    const float* __restrict__ bv,
    __half* __restrict__ Qh, __half* __restrict__ Kh, __half* __restrict__ Vth)
{
    __shared__ __align__(128) char smem[2 * STAGE_BYTES + 16];
    const uint32_t sb = smem_u32(smem);
    const int by = blockIdx.y;

    const __half* Abase;
    const __half* Bbase;
    const float* bias;
    __half* Cout;
    int m_blk;
    int omode;                       // 1 = normal fp16 out, 2 = transposed (V)
    if (by < 64) {
        m_blk = by * 128;
        Abase = qh + (size_t)m_blk * CHID;
        Bbase = Wh + 0L * CHID * CHID;
        bias = bq; Cout = Qh; omode = 1;
    } else if (by < 192) {
        m_blk = (by - 64) * 128;
        Abase = kvh + (size_t)m_blk * CHID;
        Bbase = Wh + 1L * CHID * CHID;
        bias = bk; Cout = Kh; omode = 1;
    } else {
        m_blk = (by - 192) * 128;
        Abase = kvh + (size_t)m_blk * CHID;
        Bbase = Wh + 2L * CHID * CHID;
        bias = bv; Cout = Vth; omode = 2;
    }
    const int n_blk = blockIdx.x * 128;
    Bbase += (size_t)n_blk * CHID;

    float acc[4][4][4];
#pragma unroll
    for (int i = 0; i < 4; i++)
#pragma unroll
        for (int j = 0; j < 4; j++)
#pragma unroll
            for (int r = 0; r < 4; r++) acc[i][j][r] = 0.f;

    gemm_mainloop(sb, Abase, Bbase, CHID, acc);

    const int tid = threadIdx.x;
    const int w = tid >> 5, l = tid & 31;
    const int g = l >> 2, t = l & 3;
    const int wr = (w >> 2) * 64, wc = (w & 3) * 32;

#pragma unroll
    for (int i = 0; i < 4; i++) {
        const int row0 = m_blk + wr + i * 16 + g;
        const int row1 = row0 + 8;
#pragma unroll
        for (int j = 0; j < 4; j++) {
            const int col = n_blk + wc + j * 8 + 2 * t;
            const float b0 = bias[col], b1 = bias[col + 1];
            const float c0 = acc[i][j][0] + b0, c1 = acc[i][j][1] + b1;
            const float c2 = acc[i][j][2] + b0, c3 = acc[i][j][3] + b1;
            if (omode == 1) {
                *(__half2*)&Cout[(size_t)row0 * CHID + col] = __floats2half2_rn(c0, c1);
                *(__half2*)&Cout[(size_t)row1 * CHID + col] = __floats2half2_rn(c2, c3);
            } else {
                const int b = row0 >> 11, lkv0 = row0 & 2047, lkv1 = row1 & 2047;
                __half* vt = Vth + (size_t)b * CHID * CLKV;
                vt[(size_t)(col)     * CLKV + lkv0] = __float2half(c0);
                vt[(size_t)(col + 1) * CLKV + lkv0] = __float2half(c1);
                vt[(size_t)(col)     * CLKV + lkv1] = __float2half(c2);
                vt[(size_t)(col + 1) * CLKV + lkv1] = __float2half(c3);
            }
        }
    }
}

// -------------------- generic GEMM (scores / ctx / out) ----------------------
// OMODE: 0 = f32 out, 1 = fp16 out
template <int OMODE, bool BIAS>
__global__ __launch_bounds__(256, 2) void gemm_f16(
    const __half* __restrict__ Ag, const __half* __restrict__ Bg,
    const float* __restrict__ bias, void* __restrict__ Cg,
    int Kdim, int ldc, long sA, long sB, long sC, float alpha)
{
    __shared__ __align__(128) char smem[2 * STAGE_BYTES + 16];
    const uint32_t sb = smem_u32(smem);

    const int m_blk = blockIdx.y * 128;
    const int n_blk = blockIdx.x * 128;
    const __half* Abase = Ag + (size_t)blockIdx.z * sA + (size_t)m_blk * Kdim;
    const __half* Bbase = Bg + (size_t)blockIdx.z * sB + (size_t)n_blk * Kdim;

    float acc[4][4][4];
#pragma unroll
    for (int i = 0; i < 4; i++)
#pragma unroll
        for (int j = 0; j < 4; j++)
#pragma unroll
            for (int r = 0; r < 4; r++) acc[i][j][r] = 0.f;

    gemm_mainloop(sb, Abase, Bbase, Kdim, acc);

    const int tid = threadIdx.x;
    const int w = tid >> 5, l = tid & 31;
    const int g = l >> 2, t = l & 3;
    const int wr = (w >> 2) * 64, wc = (w & 3) * 32;

#pragma unroll
    for (int i = 0; i < 4; i++) {
        const int row0 = m_blk + wr + i * 16 + g;
        const int row1 = row0 + 8;
#pragma unroll
        for (int j = 0; j < 4; j++) {
            const int col = n_blk + wc + j * 8 + 2 * t;
            float c0 = alpha * acc[i][j][0], c1 = alpha * acc[i][j][1];
            float c2 = alpha * acc[i][j][2], c3 = alpha * acc[i][j][3];
            if (BIAS) {
                const float b0 = bias[col], b1 = bias[col + 1];
                c0 += b0; c1 += b1; c2 += b0; c3 += b1;
            }
            if (OMODE == 0) {
                float* C = (float*)Cg + (size_t)blockIdx.z * sC;
                *(float2*)&C[(size_t)row0 * ldc + col] = make_float2(c0, c1);
                *(float2*)&C[(size_t)row1 * ldc + col] = make_float2(c2, c3);
            } else {
                __half* C = (__half*)Cg + (size_t)blockIdx.z * sC;
                *(__half2*)&C[(size_t)row0 * ldc + col] = __floats2half2_rn(c0, c1);
                *(__half2*)&C[(size_t)row1 * ldc + col] = __floats2half2_rn(c2, c3);
            }
        }
    }
}

// -------------------- fused prep 1: mask canonicalize + fp16 converts --------
// grid: [0,64) mask | [64, 64+8192) query convert | [64+8192, 64+8192+16384) kv
__global__ __launch_bounds__(256) void prep_fused(
    const unsigned char* __restrict__ m,
    const float4* __restrict__ q, const float4* __restrict__ kv)
{
    const int bx = blockIdx.x;
    const int tid = threadIdx.x;
    if (bx < 64) {
        // mask canonicalize (validated R3): detect int32/uint8/float32
        __shared__ int s_nz123, s_f3;
        if (tid == 0) { s_nz123 = 0; s_f3 = 0; }
        __syncthreads();
        int nz = 0, f3 = 0;
        const int base = tid * 16;
#pragma unroll
        for (int i = 0; i < 16; i++) {
            const int idx = base + i;
            const unsigned char v = m[idx];
            const int offb = idx & 3;
            if (offb != 0 && v != 0) { nz = 1; if (offb == 3 && v == 0x3F) f3 = 1; }
        }
        if (nz) atomicOr(&s_nz123, 1);
        if (f3) atomicOr(&s_f3, 1);
        __syncthreads();
        const int mode = s_f3 ? 2 : (s_nz123 ? 1 : 0);
        const long idx = (long)bx * 256 + tid;
        unsigned char out;
        if (mode == 0)      out = (((const int*)m)[idx]   != 0);
        else if (mode == 1) out = (m[idx]                 != 0);
        else                out = (((const float*)m)[idx] != 0.0f);
        g_mask[idx] = out;
    } else if (bx < 64 + 8192) {
        const long i = (long)(bx - 64) * 256 + tid;
        float4 v = q[i];
        __half2* out = (__half2*)g_qh;
        out[2 * i]     = __floats2half2_rn(v.x, v.y);
        out[2 * i + 1] = __floats2half2_rn(v.z, v.w);
    } else {
        const long i = (long)(bx - 64 - 8192) * 256 + tid;
        float4 v = kv[i];
        __half2* out = (__half2*)g_kvh;
        out[2 * i]     = __floats2half2_rn(v.x, v.y);
        out[2 * i + 1] = __floats2half2_rn(v.z, v.w);
    }
}

// -------------------- fused prep 2: 4 weight transposes (grid.z selects) -----
__global__ __launch_bounds__(256) void transpose4_h(
    const float* __restrict__ W0, const float* __restrict__ W1,
    const float* __restrict__ W2, const float* __restrict__ W3)
{
    const int z = blockIdx.z;
    const float* W = (z == 0) ? W0 : (z == 1) ? W1 : (z == 2) ? W2 : W3;
    __half* Wt = (__half*)g_Wh + (size_t)z * CHID * CHID;

    __shared__ float tbuf[32][33];
    const int bx = blockIdx.x * 32, by = blockIdx.y * 32;
    const int x = threadIdx.x & 31, y8 = threadIdx.x >> 5;
#pragma unroll
    for (int i = 0; i < 32; i += 8)
        tbuf[y8 + i][x] = W[(size_t)(by + y8 + i) * CHID + bx + x];
    __syncthreads();
#pragma unroll
    for (int i = 0; i < 32; i += 8)
        Wt[(size_t)(bx + y8 + i) * CHID + by + x] = __float2half(tbuf[x][y8 + i]);
}

// -------------------- masked softmax: f32 scores -> fp16 probs --------------
__global__ __launch_bounds__(256) void softmax_rows(const float* __restrict__ S,
                                                    __half* __restrict__ P)
{
    const int row = blockIdx.x;
    const int b   = row / CLQ;
    const float* s = S + (long)row * CLKV;
    __half* p = P + (long)row * CLKV;
    const unsigned char* mrow = g_mask + (long)b * CLKV;

    const int tid = threadIdx.x;
    const int w = tid >> 5, l = tid & 31;
    float v[8];
    float mx = -3.0e38f;
#pragma unroll
    for (int i = 0; i < 8; i++) {
        const int k = tid + i * 256;
        const float x = mrow[k] ? s[k] : -1e9f;
        v[i] = x; mx = fmaxf(mx, x);
    }
    __shared__ float red[8];
#pragma unroll
    for (int o = 16; o > 0; o >>= 1) mx = fmaxf(mx, __shfl_xor_sync(0xffffffffu, mx, o));
    if (l == 0) red[w] = mx;
    __syncthreads();
    if (w == 0) {
        float m8 = (l < 8) ? red[l] : -3.0e38f;
#pragma unroll
        for (int o = 4; o > 0; o >>= 1) m8 = fmaxf(m8, __shfl_xor_sync(0xffffffffu, m8, o));
        if (l == 0) red[0] = m8;
    }
    __syncthreads();
    mx = red[0];
    __syncthreads();
    float sum = 0.f;
#pragma unroll
    for (int i = 0; i < 8; i++) { v[i] = __expf(v[i] - mx); sum += v[i]; }
#pragma unroll
    for (int o = 16; o > 0; o >>= 1) sum += __shfl_xor_sync(0xffffffffu, sum, o);
    if (l == 0) red[w] = sum;
    __syncthreads();
    if (w == 0) {
        float s8 = (l < 8) ? red[l] : 0.f;
#pragma unroll
        for (int o = 4; o > 0; o >>= 1) s8 += __shfl_xor_sync(0xffffffffu, s8, o);
        if (l == 0) red[0] = s8;
    }
    __syncthreads();
    const float inv = 1.0f / red[0];
#pragma unroll
    for (int i = 0; i < 8; i++) p[tid + i * 256] = __float2half(v[i] * inv);
}

// -------------------- launch -------------------------------------------------
extern "C" void kernel_launch(void* const* d_in, const int* in_sizes, int n_in,
                              void* d_out, int out_size)
{
    (void)in_sizes; (void)n_in; (void)out_size;
    const float* query = (const float*)d_in[0];
    const float* keyv  = (const float*)d_in[1];
    const unsigned char* mask = (const unsigned char*)d_in[2];
    const float* Wq = (const float*)d_in[3];
    const float* bq = (const float*)d_in[4];
    const float* Wk = (const float*)d_in[5];
    const float* bk = (const float*)d_in[6];
    const float* Wv = (const float*)d_in[7];
    const float* bv = (const float*)d_in[8];
    const float* Wo = (const float*)d_in[9];
    const float* bo = (const float*)d_in[10];
    float* out = (float*)d_out;

    __half *qh, *kvh, *Qh, *Kh, *Vth, *Ph, *Ch, *Wh;
    float* Sf;
    cudaGetSymbolAddress((void**)&qh,  g_qh);
    cudaGetSymbolAddress((void**)&kvh, g_kvh);
    cudaGetSymbolAddress((void**)&Qh,  g_Qh);
    cudaGetSymbolAddress((void**)&Kh,  g_Kh);
    cudaGetSymbolAddress((void**)&Vth, g_Vth);
    cudaGetSymbolAddress((void**)&Ph,  g_Ph);
    cudaGetSymbolAddress((void**)&Ch,  g_Ch);
    cudaGetSymbolAddress((void**)&Sf,  g_S);
    cudaGetSymbolAddress((void**)&Wh,  g_Wh);

    // launch 0: mask + fp16 converts (fused)
    prep_fused<<<64 + 8192 + 16384, 256>>>(mask, (const float4*)query, (const float4*)keyv);
    // launch 1: all 4 weight transposes (fused)
    transpose4_h<<<dim3(32, 32, 4), 256>>>(Wq, Wk, Wv, Wo);
    // launch 2: merged Q/K/V projections (2560 CTAs)
    proj_all<<<dim3(8, 320, 1), 256>>>(qh, kvh, Wh, bq, bk, bv, Qh, Kh, Vth);
    // launch 3: S = (Q K^T)/32 -> f32 (batched)
    gemm_f16<0, false><<<dim3(16, 8, CB), 256>>>(
        Qh, Kh, nullptr, Sf, CHID, CLKV,
        (long)CLQ * CHID, (long)CLKV * CHID, (long)CLQ * CLKV, 0.03125f);
    // launch 4: P = softmax(mask(S)) -> fp16
    softmax_rows<<<CB * CLQ, 256>>>(Sf, Ph);
    // launch 5 (ncu -s 5 capture slot): Ctx = P @ Vt^T -> fp16 (batched)
    gemm_f16<1, false><<<dim3(8, 8, CB), 256>>>(
        Ph, Vth, nullptr, Ch, CLKV, CHID,
        (long)CLQ * CLKV, (long)CHID * CLKV, (long)CLQ * CHID, 1.f);
    // launch 6: out = Ctx @ WoT + bo -> f32
    gemm_f16<0, true><<<dim3(8, 64, 1), 256>>>(
        Ch, Wh + 3L * CHID * CHID, bo, out, CHID, CHID, 0, 0, 0, 1.f);
}

// round 15
// speedup vs baseline: 2.3620x; 1.0826x over previous
#include <cuda_runtime.h>
#include <cuda_fp16.h>
#include <cstdint>

// ---------------------------------------------------------------------------
// CrossModalAttention, plain sm_100, legacy mma.sync FP16 (m16n8k16, f32 acc).
// R12: 698us, scores tensor=48.0% with L1=45.4% -> smem crossbar and tensor
// pipe co-binding (~1:1 wavefronts:HMMA). R13: warp tile 64x32 -> 64x64
// (CTA 128x256, 8 warps): smem bytes per FLOP -31%. 64B rows + XOR swizzle
// (chunk ^ ((row>>1)&3)), stage 24KB, double buffer = exactly 48KB static.
// Fragment mapping identical to validated R12; only wc scale + swizzle differ.
// Static smem only; NO cudaFuncSetAttribute (proven container-killer).
// ---------------------------------------------------------------------------

#define CB    8
#define CLQ   1024
#define CLKV  2048
#define CHID  1024

// -------------------- scratch (allocation-free: device globals) -------------
__device__ __align__(16) __half g_qh [(size_t)CB * CLQ  * CHID];  // query fp16
__device__ __align__(16) __half g_kvh[(size_t)CB * CLKV * CHID];  // key_value fp16
__device__ __align__(16) __half g_Qh [(size_t)CB * CLQ  * CHID];
__device__ __align__(16) __half g_Kh [(size_t)CB * CLKV * CHID];
__device__ __align__(16) __half g_Vth[(size_t)CB * CHID * CLKV];  // V transposed [b][h][lkv]
__device__ __align__(16) __half g_Ph [(size_t)CB * CLQ  * CLKV];  // softmax probs
__device__ __align__(16) __half g_Ch [(size_t)CB * CLQ  * CHID];  // context
__device__ __align__(16) float  g_S  [(size_t)CB * CLQ  * CLKV];  // raw scores f32
__device__ __align__(16) __half g_Wh [4][(size_t)CHID * CHID];    // Wq^T..Wo^T fp16
__device__ unsigned char g_mask[(size_t)CB * CLKV];

// -------------------- helpers ----------------------------------------------
__device__ __forceinline__ uint32_t smem_u32(const void* p) {
    uint32_t a;
    asm("{ .reg .u64 t; cvta.to.shared.u64 t, %1; cvt.u32.u64 %0, t; }" : "=r"(a) : "l"(p));
    return a;
}
__device__ __forceinline__ void cpa16(uint32_t s, const void* g) {
    asm volatile("cp.async.cg.shared.global [%0], [%1], 16;" :: "r"(s), "l"(g));
}
#define CP_COMMIT() asm volatile("cp.async.commit_group;" ::: "memory")
#define CP_WAIT1()  asm volatile("cp.async.wait_group 1;" ::: "memory")

__device__ __forceinline__ void mma_f16(float* c, const uint32_t* a, const uint32_t* b) {
    asm volatile(
        "mma.sync.aligned.m16n8k16.row.col.f32.f16.f16.f32 "
        "{%0,%1,%2,%3}, {%4,%5,%6,%7}, {%8,%9}, {%0,%1,%2,%3};\n"
        : "+f"(c[0]), "+f"(c[1]), "+f"(c[2]), "+f"(c[3])
        : "r"(a[0]), "r"(a[1]), "r"(a[2]), "r"(a[3]), "r"(b[0]), "r"(b[1]));
}
__device__ __forceinline__ void ldsm4(uint32_t* r, uint32_t a) {
    asm volatile("ldmatrix.sync.aligned.m8n8.x4.shared.b16 {%0,%1,%2,%3}, [%4];"
        : "=r"(r[0]), "=r"(r[1]), "=r"(r[2]), "=r"(r[3]) : "r"(a));
}

// -------------------- shared GEMM machinery ---------------------------------
// CTA tile 128x256, k-chunk 32 halves (= 64B row), 8 warps of 64x64.
// Rows stored at 64B stride with XOR swizzle: phys_chunk = chunk ^ ((row>>1)&3)
//   -> ldmatrix phase banks 16*(r&1) + 4*chunk cover all 32: conflict-free.
// Stage = A(128x64B)=8KB + B(256x64B)=16KB = 24KB; x2 stages = 49152B (48KB).
static constexpr int A_BYTES     = 128 * 64;          // 8192
static constexpr int B_BYTES     = 256 * 64;          // 16384
static constexpr int STAGE_BYTES = A_BYTES + B_BYTES; // 24576

// Mainloop: C_tile(128x256) = A[M,K] @ B[N,K]^T, swizzled ldmatrix loads.
__device__ __forceinline__ void gemm_mainloop(
    uint32_t sb,
    const __half* __restrict__ Abase, const __half* __restrict__ Bbase,
    int Kdim, float acc[4][8][4])
{
    const int tid = threadIdx.x;
    const int r   = tid >> 2;                 // base row 0..63
    const int cch = tid & 3;                  // logical 16B chunk 0..3
    const int pc  = cch ^ ((tid >> 3) & 3);   // physical chunk (swizzled); same for all row+64k
    const uint32_t so = (uint32_t)(r * 64 + pc * 16);
    const int NC = Kdim / 32;

    auto load = [&](int kc, int st) {
        const uint32_t s0 = sb + st * STAGE_BYTES;
        const __half* ag = Abase + (size_t)r * Kdim + kc * 32 + cch * 8;
        const __half* bg = Bbase + (size_t)r * Kdim + kc * 32 + cch * 8;
        // A rows r, r+64
        cpa16(s0 + so,                    ag);
        cpa16(s0 + so + 64 * 64,          ag + (size_t)64 * Kdim);
        // B rows r, r+64, r+128, r+192
        cpa16(s0 + A_BYTES + so,          bg);
        cpa16(s0 + A_BYTES + so + 64*64,  bg + (size_t)64  * Kdim);
        cpa16(s0 + A_BYTES + so + 128*64, bg + (size_t)128 * Kdim);
        cpa16(s0 + A_BYTES + so + 192*64, bg + (size_t)192 * Kdim);
    };

    const int w = tid >> 5, l = tid & 31;
    const int wr = (w >> 2) * 64;             // warp M offset 0/64
    const int wc = (w & 3) * 64;              // warp N offset 0/64/128/192

    // ldmatrix per-thread offsets (x4: matrix idx = l>>3, row-in-matrix = l&7)
    const int lr   = l & 7;
    const int seg  = (l >> 3) & 1;
    const int seg2 = (l >> 4) & 1;
    uint32_t aoff[4][2];
#pragma unroll
    for (int i = 0; i < 4; i++)
#pragma unroll
        for (int ks = 0; ks < 2; ks++) {
            const int rowA = wr + i * 16 + lr + seg * 8;
            const int chA  = (ks * 2 + seg2) ^ ((rowA >> 1) & 3);
            aoff[i][ks] = (uint32_t)(rowA * 64 + chA * 16);
        }
    uint32_t boff[4][2];
#pragma unroll
    for (int jp = 0; jp < 4; jp++)
#pragma unroll
        for (int ks = 0; ks < 2; ks++) {
            const int rowB = wc + jp * 16 + seg2 * 8 + lr;
            const int chB  = (ks * 2 + seg) ^ ((rowB >> 1) & 3);
            boff[jp][ks] = (uint32_t)(A_BYTES + rowB * 64 + chB * 16);
        }

    load(0, 0); CP_COMMIT();

    for (int c = 0; c < NC; c++) {
        if (c + 1 < NC) load(c + 1, (c + 1) & 1);
        CP_COMMIT();
        CP_WAIT1();
        __syncthreads();

        const uint32_t st = sb + (c & 1) * STAGE_BYTES;
#pragma unroll
        for (int ks = 0; ks < 2; ks++) {
            uint32_t af[4][4];
#pragma unroll
            for (int i = 0; i < 4; i++) ldsm4(af[i], st + aoff[i][ks]);
            uint32_t bq[4][4];
#pragma unroll
            for (int jp = 0; jp < 4; jp++) ldsm4(bq[jp], st + boff[jp][ks]);
#pragma unroll
            for (int i = 0; i < 4; i++)
#pragma unroll
                for (int j = 0; j < 8; j++)
                    mma_f16(acc[i][j], af[i], &bq[j >> 1][(j & 1) * 2]);
        }
        __syncthreads();
    }
}

// -------------------- merged Q/K/V projection (one launch, 1280 CTAs) -------
// grid (4, 320): by<64 -> Q proj; by<192 -> K proj; else V proj (transposed).
__global__ __launch_bounds__(256, 1) void proj_all(
    const __half* __restrict__ qh, const __half* __restrict__ kvh,
    const __half* __restrict__ Wh,
    const float* __restrict__ bq, const float* __restrict__ bk,
    const float* __restrict__ bv,
    __half* __restrict__ Qh, __half* __restrict__ Kh, __half* __restrict__ Vth)
{
    __shared__ __align__(128) char smem[2 * STAGE_BYTES];
    const uint32_t sb = smem_u32(smem);
    const int by = blockIdx.y;

    const __half* Abase;
    const __half* Bbase;
    const float* bias;
    __half* Cout;
    int m_blk;
    int omode;                       // 1 = normal fp16 out, 2 = transposed (V)
    if (by < 64) {
        m_blk = by * 128;
        Abase = qh + (size_t)m_blk * CHID;
        Bbase = Wh + 0L * CHID * CHID;
        bias = bq; Cout = Qh; omode = 1;
    } else if (by < 192) {
        m_blk = (by - 64) * 128;
        Abase = kvh + (size_t)m_blk * CHID;
        Bbase = Wh + 1L * CHID * CHID;
        bias = bk; Cout = Kh; omode = 1;
    } else {
        m_blk = (by - 192) * 128;
        Abase = kvh + (size_t)m_blk * CHID;
        Bbase = Wh + 2L * CHID * CHID;
        bias = bv; Cout = Vth; omode = 2;
    }
    const int n_blk = blockIdx.x * 256;
    Bbase += (size_t)n_blk * CHID;

    float acc[4][8][4];
#pragma unroll
    for (int i = 0; i < 4; i++)
#pragma unroll
        for (int j = 0; j < 8; j++)
#pragma unroll
            for (int rr = 0; rr < 4; rr++) acc[i][j][rr] = 0.f;

    gemm_mainloop(sb, Abase, Bbase, CHID, acc);

    const int tid = threadIdx.x;
    const int w = tid >> 5, l = tid & 31;
    const int g = l >> 2, t = l & 3;
    const int wr = (w >> 2) * 64, wc = (w & 3) * 64;

#pragma unroll
    for (int i = 0; i < 4; i++) {
        const int row0 = m_blk + wr + i * 16 + g;
        const int row1 = row0 + 8;
#pragma unroll
        for (int j = 0; j < 8; j++) {
            const int col = n_blk + wc + j * 8 + 2 * t;
            const float b0 = bias[col], b1 = bias[col + 1];
            const float c0 = acc[i][j][0] + b0, c1 = acc[i][j][1] + b1;
            const float c2 = acc[i][j][2] + b0, c3 = acc[i][j][3] + b1;
            if (omode == 1) {
                *(__half2*)&Cout[(size_t)row0 * CHID + col] = __floats2half2_rn(c0, c1);
                *(__half2*)&Cout[(size_t)row1 * CHID + col] = __floats2half2_rn(c2, c3);
            } else {
                const int b = row0 >> 11, lkv0 = row0 & 2047, lkv1 = row1 & 2047;
                __half* vt = Vth + (size_t)b * CHID * CLKV;
                vt[(size_t)(col)     * CLKV + lkv0] = __float2half(c0);
                vt[(size_t)(col + 1) * CLKV + lkv0] = __float2half(c1);
                vt[(size_t)(col)     * CLKV + lkv1] = __float2half(c2);
                vt[(size_t)(col + 1) * CLKV + lkv1] = __float2half(c3);
            }
        }
    }
}

// -------------------- generic GEMM (scores / ctx / out) ----------------------
// OMODE: 0 = f32 out, 1 = fp16 out
template <int OMODE, bool BIAS>
__global__ __launch_bounds__(256, 1) void gemm_f16(
    const __half* __restrict__ Ag, const __half* __restrict__ Bg,
    const float* __restrict__ bias, void* __restrict__ Cg,
    int Kdim, int ldc, long sA, long sB, long sC, float alpha)
{
    __shared__ __align__(128) char smem[2 * STAGE_BYTES];
    const uint32_t sb = smem_u32(smem);

    const int m_blk = blockIdx.y * 128;
    const int n_blk = blockIdx.x * 256;
    const __half* Abase = Ag + (size_t)blockIdx.z * sA + (size_t)m_blk * Kdim;
    const __half* Bbase = Bg + (size_t)blockIdx.z * sB + (size_t)n_blk * Kdim;

    float acc[4][8][4];
#pragma unroll
    for (int i = 0; i < 4; i++)
#pragma unroll
        for (int j = 0; j < 8; j++)
#pragma unroll
            for (int rr = 0; rr < 4; rr++) acc[i][j][rr] = 0.f;

    gemm_mainloop(sb, Abase, Bbase, Kdim, acc);

    const int tid = threadIdx.x;
    const int w = tid >> 5, l = tid & 31;
    const int g = l >> 2, t = l & 3;
    const int wr = (w >> 2) * 64, wc = (w & 3) * 64;

#pragma unroll
    for (int i = 0; i < 4; i++) {
        const int row0 = m_blk + wr + i * 16 + g;
        const int row1 = row0 + 8;
#pragma unroll
        for (int j = 0; j < 8; j++) {
            const int col = n_blk + wc + j * 8 + 2 * t;
            float c0 = alpha * acc[i][j][0], c1 = alpha * acc[i][j][1];
            float c2 = alpha * acc[i][j][2], c3 = alpha * acc[i][j][3];
            if (BIAS) {
                const float b0 = bias[col], b1 = bias[col + 1];
                c0 += b0; c1 += b1; c2 += b0; c3 += b1;
            }
            if (OMODE == 0) {
                float* C = (float*)Cg + (size_t)blockIdx.z * sC;
                *(float2*)&C[(size_t)row0 * ldc + col] = make_float2(c0, c1);
                *(float2*)&C[(size_t)row1 * ldc + col] = make_float2(c2, c3);
            } else {
                __half* C = (__half*)Cg + (size_t)blockIdx.z * sC;
                *(__half2*)&C[(size_t)row0 * ldc + col] = __floats2half2_rn(c0, c1);
                *(__half2*)&C[(size_t)row1 * ldc + col] = __floats2half2_rn(c2, c3);
            }
        }
    }
}

// -------------------- fused prep 1: mask canonicalize + fp16 converts --------
// grid: [0,64) mask | [64, 64+8192) query convert | [64+8192, 64+8192+16384) kv
__global__ __launch_bounds__(256) void prep_fused(
    const unsigned char* __restrict__ m,
    const float4* __restrict__ q, const float4* __restrict__ kv)
{
    const int bx = blockIdx.x;
    const int tid = threadIdx.x;
    if (bx < 64) {
        // mask canonicalize (validated R3): detect int32/uint8/float32
        __shared__ int s_nz123, s_f3;
        if (tid == 0) { s_nz123 = 0; s_f3 = 0; }
        __syncthreads();
        int nz = 0, f3 = 0;
        const int base = tid * 16;
#pragma unroll
        for (int i = 0; i < 16; i++) {
            const int idx = base + i;
            const unsigned char v = m[idx];
            const int offb = idx & 3;
            if (offb != 0 && v != 0) { nz = 1; if (offb == 3 && v == 0x3F) f3 = 1; }
        }
        if (nz) atomicOr(&s_nz123, 1);
        if (f3) atomicOr(&s_f3, 1);
        __syncthreads();
        const int mode = s_f3 ? 2 : (s_nz123 ? 1 : 0);
        const long idx = (long)bx * 256 + tid;
        unsigned char out;
        if (mode == 0)      out = (((const int*)m)[idx]   != 0);
        else if (mode == 1) out = (m[idx]                 != 0);
        else                out = (((const float*)m)[idx] != 0.0f);
        g_mask[idx] = out;
    } else if (bx < 64 + 8192) {
        const long i = (long)(bx - 64) * 256 + tid;
        float4 v = q[i];
        __half2* out = (__half2*)g_qh;
        out[2 * i]     = __floats2half2_rn(v.x, v.y);
        out[2 * i + 1] = __floats2half2_rn(v.z, v.w);
    } else {
        const long i = (long)(bx - 64 - 8192) * 256 + tid;
        float4 v = kv[i];
        __half2* out = (__half2*)g_kvh;
        out[2 * i]     = __floats2half2_rn(v.x, v.y);
        out[2 * i + 1] = __floats2half2_rn(v.z, v.w);
    }
}

// -------------------- fused prep 2: 4 weight transposes (grid.z selects) -----
__global__ __launch_bounds__(256) void transpose4_h(
    const float* __restrict__ W0, const float* __restrict__ W1,
    const float* __restrict__ W2, const float* __restrict__ W3)
{
    const int z = blockIdx.z;
    const float* W = (z == 0) ? W0 : (z == 1) ? W1 : (z == 2) ? W2 : W3;
    __half* Wt = (__half*)g_Wh + (size_t)z * CHID * CHID;

    __shared__ float tbuf[32][33];
    const int bx = blockIdx.x * 32, by = blockIdx.y * 32;
    const int x = threadIdx.x & 31, y8 = threadIdx.x >> 5;
#pragma unroll
    for (int i = 0; i < 32; i += 8)
        tbuf[y8 + i][x] = W[(size_t)(by + y8 + i) * CHID + bx + x];
    __syncthreads();
#pragma unroll
    for (int i = 0; i < 32; i += 8)
        Wt[(size_t)(bx + y8 + i) * CHID + by + x] = __float2half(tbuf[x][y8 + i]);
}

// -------------------- masked softmax: f32 scores -> fp16 probs --------------
__global__ __launch_bounds__(256) void softmax_rows(const float* __restrict__ S,
                                                    __half* __restrict__ P)
{
    const int row = blockIdx.x;
    const int b   = row / CLQ;
    const float* s = S + (long)row * CLKV;
    __half* p = P + (long)row * CLKV;
    const unsigned char* mrow = g_mask + (long)b * CLKV;

    const int tid = threadIdx.x;
    const int w = tid >> 5, l = tid & 31;
    float v[8];
    float mx = -3.0e38f;
#pragma unroll
    for (int i = 0; i < 8; i++) {
        const int k = tid + i * 256;
        const float x = mrow[k] ? s[k] : -1e9f;
        v[i] = x; mx = fmaxf(mx, x);
    }
    __shared__ float red[8];
#pragma unroll
    for (int o = 16; o > 0; o >>= 1) mx = fmaxf(mx, __shfl_xor_sync(0xffffffffu, mx, o));
    if (l == 0) red[w] = mx;
    __syncthreads();
    if (w == 0) {
        float m8 = (l < 8) ? red[l] : -3.0e38f;
#pragma unroll
        for (int o = 4; o > 0; o >>= 1) m8 = fmaxf(m8, __shfl_xor_sync(0xffffffffu, m8, o));
        if (l == 0) red[0] = m8;
    }
    __syncthreads();
    mx = red[0];
    __syncthreads();
    float sum = 0.f;
#pragma unroll
    for (int i = 0; i < 8; i++) { v[i] = __expf(v[i] - mx); sum += v[i]; }
#pragma unroll
    for (int o = 16; o > 0; o >>= 1) sum += __shfl_xor_sync(0xffffffffu, sum, o);
    if (l == 0) red[w] = sum;
    __syncthreads();
    if (w == 0) {
        float s8 = (l < 8) ? red[l] : 0.f;
#pragma unroll
        for (int o = 4; o > 0; o >>= 1) s8 += __shfl_xor_sync(0xffffffffu, s8, o);
        if (l == 0) red[0] = s8;
    }
    __syncthreads();
    const float inv = 1.0f / red[0];
#pragma unroll
    for (int i = 0; i < 8; i++) p[tid + i * 256] = __float2half(v[i] * inv);
}

// -------------------- launch -------------------------------------------------
extern "C" void kernel_launch(void* const* d_in, const int* in_sizes, int n_in,
                              void* d_out, int out_size)
{
    (void)in_sizes; (void)n_in; (void)out_size;
    const float* query = (const float*)d_in[0];
    const float* keyv  = (const float*)d_in[1];
    const unsigned char* mask = (const unsigned char*)d_in[2];
    const float* Wq = (const float*)d_in[3];
    const float* bq = (const float*)d_in[4];
    const float* Wk = (const float*)d_in[5];
    const float* bk = (const float*)d_in[6];
    const float* Wv = (const float*)d_in[7];
    const float* bv = (const float*)d_in[8];
    const float* Wo = (const float*)d_in[9];
    const float* bo = (const float*)d_in[10];
    float* out = (float*)d_out;

    __half *qh, *kvh, *Qh, *Kh, *Vth, *Ph, *Ch, *Wh;
    float* Sf;
    cudaGetSymbolAddress((void**)&qh,  g_qh);
    cudaGetSymbolAddress((void**)&kvh, g_kvh);
    cudaGetSymbolAddress((void**)&Qh,  g_Qh);
    cudaGetSymbolAddress((void**)&Kh,  g_Kh);
    cudaGetSymbolAddress((void**)&Vth, g_Vth);
    cudaGetSymbolAddress((void**)&Ph,  g_Ph);
    cudaGetSymbolAddress((void**)&Ch,  g_Ch);
    cudaGetSymbolAddress((void**)&Sf,  g_S);
    cudaGetSymbolAddress((void**)&Wh,  g_Wh);

    // launch 0: mask + fp16 converts (fused)
    prep_fused<<<64 + 8192 + 16384, 256>>>(mask, (const float4*)query, (const float4*)keyv);
    // launch 1: all 4 weight transposes (fused)
    transpose4_h<<<dim3(32, 32, 4), 256>>>(Wq, Wk, Wv, Wo);
    // launch 2: merged Q/K/V projections (1280 CTAs, tiles 128x256)
    proj_all<<<dim3(4, 320, 1), 256>>>(qh, kvh, Wh, bq, bk, bv, Qh, Kh, Vth);
    // launch 3: S = (Q K^T)/32 -> f32 (batched)
    gemm_f16<0, false><<<dim3(8, 8, CB), 256>>>(
        Qh, Kh, nullptr, Sf, CHID, CLKV,
        (long)CLQ * CHID, (long)CLKV * CHID, (long)CLQ * CLKV, 0.03125f);
    // launch 4: P = softmax(mask(S)) -> fp16
    softmax_rows<<<CB * CLQ, 256>>>(Sf, Ph);
    // launch 5 (ncu -s 5 capture slot): Ctx = P @ Vt^T -> fp16 (batched)
    gemm_f16<1, false><<<dim3(4, 8, CB), 256>>>(
        Ph, Vth, nullptr, Ch, CLKV, CHID,
        (long)CLQ * CLKV, (long)CHID * CLKV, (long)CLQ * CHID, 1.f);
    // launch 6: out = Ctx @ WoT + bo -> f32
    gemm_f16<0, true><<<dim3(4, 64, 1), 256>>>(
        Ch, Wh + 3L * CHID * CHID, bo, out, CHID, CHID, 0, 0, 0, 1.f);
}